// round 6
// baseline (speedup 1.0000x reference)
#include <cuda_runtime.h>

#define BATCH 2
#define DIM   256
#define HEADS 8
#define HD    32
#define RES   256
#define FWS   8
#define BN    512            // BATCH * 16 * 16 windows
#define NPIX  64
#define ATTN_SCALE 0.17677669529663689f

// ---------------- device scratch ----------------
__device__ float g_sub[(size_t)4 * BN * DIM * NPIX];          // [s][w][c][n]  134.2 MB
__device__ float g_bias[HEADS * NPIX * NPIX];                 // 128 KB
__device__ float g_attn[(size_t)BN * HEADS * NPIX * NPIX];    // softmaxed attn, 67 MB
__device__ float g_cat[(size_t)BN * DIM * NPIX];              // relu'd cat, 33.5 MB
__device__ float g_pwT[DIM * DIM];                            // transposed proj weight

typedef unsigned long long u64;

__device__ __forceinline__ u64 pack2(float lo, float hi) {
    u64 r; asm("mov.b64 %0,{%1,%2};" : "=l"(r) : "f"(lo), "f"(hi)); return r;
}
__device__ __forceinline__ void unpack2(u64 v, float& a, float& b) {
    asm("mov.b64 {%0,%1},%2;" : "=f"(a), "=f"(b) : "l"(v));
}
__device__ __forceinline__ void fma2(u64& d, u64 a, u64 b) {
    asm("fma.rn.f32x2 %0,%1,%2,%0;" : "+l"(d) : "l"(a), "l"(b));
}

// ---------------- bias gather ----------------
__global__ void wwa_bias(const float* __restrict__ ab, const int* __restrict__ idxs, int n_off) {
    int idx = blockIdx.x * 256 + threadIdx.x;
    int i = idx >> 12, r = idx & 4095;
    g_bias[idx] = ab[i * n_off + idxs[r]];
}

// ---------------- proj weight transpose: g_pwT[c][o] = pw[o][c] -------------
__global__ void wwa_pwT(const float* __restrict__ pw) {
    __shared__ float tile[32][33];
    int bo = blockIdx.x & 7, bc = blockIdx.x >> 3;
    int lx = threadIdx.x & 31, ly = threadIdx.x >> 5;   // 256 threads: 32x8
    for (int r = ly; r < 32; r += 8)
        tile[r][lx] = pw[(bo * 32 + r) * 256 + bc * 32 + lx];
    __syncthreads();
    for (int r = ly; r < 32; r += 8)
        g_pwT[(bc * 32 + r) * 256 + bo * 32 + lx] = tile[lx][r];
}

// ---------------- wavelet transform ----------------
__global__ void wwa_wt(const float* __restrict__ x, const float* __restrict__ wf) {
    int g = blockIdx.x * 256 + threadIdx.x;
    int pair = g & 31;
    int c = (g >> 5) & 255;
    int w = g >> 13;
    int b = w >> 8, wy = (w >> 4) & 15, wx = w & 15;
    int n0 = pair * 2;
    int p = wy * 8 + (n0 >> 3);
    int q0 = wx * 8 + (n0 & 7);
    const float* xp = x + ((size_t)(b * DIM + c) * RES + 2 * p) * RES + 2 * q0;
    float4 r0 = *(const float4*)xp;
    float4 r1 = *(const float4*)(xp + RES);
    const float4* wf4 = (const float4*)wf;
    float* dst = g_sub + ((size_t)w * DIM + c) * NPIX + n0;
#pragma unroll
    for (int s = 0; s < 4; s++) {
        float4 f = wf4[4 * c + s];
        float o0 = r0.x * f.x + r0.y * f.y + r1.x * f.z + r1.y * f.w;
        float o1 = r0.z * f.x + r0.w * f.y + r1.z * f.z + r1.w * f.w;
        *(float2*)(dst + (size_t)s * BN * DIM * NPIX) = make_float2(o0, o1);
    }
}

// ---------------- attention precompute: conv -> QK^T -> softmax -> g_attn ----
#define A_LH  0                      // padded conv tile [32][145] = 4640
#define A_DWW 4640                   // 800
#define A_DWB 5440                   // 32
#define A_Q   5472                   // [64][33] = 2112
#define A_K   7584                   // [32][66] = 2112
#define A_TOT 9696

__global__ __launch_bounds__(256)
void wwa_attn(const float* __restrict__ dww, const float* __restrict__ dwb) {
    __shared__ float sm[A_TOT];
    const int t = threadIdx.x;
    const int wh = blockIdx.x;
    const int w = wh >> 3, i = wh & 7;
    const float* lhp = g_sub + ((size_t)BN + w) * DIM * NPIX + i * HD * NPIX;
    const float* hlp = g_sub + ((size_t)2 * BN + w) * DIM * NPIX + i * HD * NPIX;

    for (int k = t; k < 4640; k += 256) sm[A_LH + k] = 0.f;
    __syncthreads();
    for (int k = t; k < 2048; k += 256) {
        int c = k >> 6, n = k & 63;
        sm[A_LH + c * 145 + (n >> 3) * 12 + (n & 7) + 26] = lhp[k];  // (+2,+2) pad
        sm[A_K + c * 66 + n] = hlp[k];
    }
    for (int k = t; k < 800; k += 256) sm[A_DWW + k] = dww[i * 800 + k];
    if (t < 32) sm[A_DWB + t] = dwb[i * 32 + t];
    __syncthreads();

    // depthwise 5x5 conv (pad 2) -> q[n][d]
    {
        int d = t & 31, py = t >> 5;
        float wl[25];
#pragma unroll
        for (int k = 0; k < 25; k++) wl[k] = sm[A_DWW + d * 25 + k];
        float bb = sm[A_DWB + d];
        const float* base = &sm[A_LH + d * 145 + py * 12];
#pragma unroll
        for (int qx = 0; qx < 8; qx++) {
            float acc = bb;
#pragma unroll
            for (int ii = 0; ii < 5; ii++)
#pragma unroll
                for (int jj = 0; jj < 5; jj++)
                    acc += base[ii * 12 + qx + jj] * wl[ii * 5 + jj];
            sm[A_Q + (py * 8 + qx) * 33 + d] = acc;
        }
    }
    __syncthreads();

    // attn = softmax(q k^T * scale + bias) -> global
    {
        int rg = t >> 4, cg = t & 15, m0 = cg * 4;
        u64 acc[4][2] = {};
#pragma unroll 4
        for (int d = 0; d < 32; d++) {
            u64 k0 = *(const u64*)&sm[A_K + d * 66 + m0];
            u64 k1 = *(const u64*)&sm[A_K + d * 66 + m0 + 2];
#pragma unroll
            for (int r = 0; r < 4; r++) {
                float qv = sm[A_Q + (rg * 4 + r) * 33 + d];
                u64 q2 = pack2(qv, qv);
                fma2(acc[r][0], q2, k0);
                fma2(acc[r][1], q2, k1);
            }
        }
        float* ap = g_attn + (size_t)wh * 4096;
#pragma unroll
        for (int r = 0; r < 4; r++) {
            int n = rg * 4 + r;
            float v0, v1, v2, v3;
            unpack2(acc[r][0], v0, v1);
            unpack2(acc[r][1], v2, v3);
            const float4 bv = *(const float4*)&g_bias[i * 4096 + n * 64 + m0];
            v0 = v0 * ATTN_SCALE + bv.x; v1 = v1 * ATTN_SCALE + bv.y;
            v2 = v2 * ATTN_SCALE + bv.z; v3 = v3 * ATTN_SCALE + bv.w;
            float mx = fmaxf(fmaxf(v0, v1), fmaxf(v2, v3));
#pragma unroll
            for (int off = 8; off >= 1; off >>= 1)
                mx = fmaxf(mx, __shfl_xor_sync(0xffffffffu, mx, off));
            v0 = __expf(v0 - mx); v1 = __expf(v1 - mx);
            v2 = __expf(v2 - mx); v3 = __expf(v3 - mx);
            float s = v0 + v1 + v2 + v3;
#pragma unroll
            for (int off = 8; off >= 1; off >>= 1)
                s += __shfl_xor_sync(0xffffffffu, s, off);
            float inv = __fdividef(1.f, s);
            *(float4*)&ap[n * 64 + m0] = make_float4(v0 * inv, v1 * inv, v2 * inv, v3 * inv);
        }
    }
}

// ---------------- cascade AV only -> g_cat (relu'd) --------------------------
__global__ __launch_bounds__(512, 3)
void wwa_casc() {
    __shared__ float sV[32 * 66], sT[32 * 66], sA[64 * 68];
    const int t = threadIdx.x, w = blockIdx.x;
    const float* subll = g_sub + (size_t)w * 16384;
    float* catw = g_cat + (size_t)w * 16384;

#pragma unroll 1
    for (int i = 0; i < 8; i++) {
        __syncthreads();
        const float4* ap4 = (const float4*)(g_attn + (size_t)(w * 8 + i) * 4096);
        for (int k = t; k < 1024; k += 512) {
            int n = k >> 4, m4 = k & 15;
            *(float4*)&sA[n * 68 + m4 * 4] = ap4[k];
        }
        const float* llp = subll + i * 2048;
        if (i == 0) {
            for (int k = t; k < 1024; k += 512) {
                int d = k >> 5, m2 = k & 31;
                *(float2*)&sV[d * 66 + m2 * 2] = *(const float2*)&llp[d * 64 + m2 * 2];
            }
        } else {
            for (int k = t; k < 1024; k += 512) {
                int d = k >> 5, m2 = k & 31;
                float2 l2 = *(const float2*)&llp[d * 64 + m2 * 2];
                float2 t2 = *(const float2*)&sT[d * 66 + m2 * 2];
                *(float2*)&sV[d * 66 + m2 * 2] = make_float2(l2.x + t2.x, l2.y + t2.y);
            }
        }
        __syncthreads();

        const int d = t & 31, n0 = (t >> 5) * 4;
        u64 acc[4] = {};
#pragma unroll
        for (int m = 0; m < 64; m += 4) {
            u64 v0 = *(const u64*)&sV[d * 66 + m];
            u64 v1 = *(const u64*)&sV[d * 66 + m + 2];
#pragma unroll
            for (int j = 0; j < 4; j++) {
                longlong2 a2 = *(const longlong2*)&sA[(n0 + j) * 68 + m];
                fma2(acc[j], v0, (u64)a2.x);
                fma2(acc[j], v1, (u64)a2.y);
            }
        }
#pragma unroll
        for (int j = 0; j < 4; j++) {
            float lo, hi; unpack2(acc[j], lo, hi);
            sT[d * 66 + n0 + j] = lo + hi;
        }
        __syncthreads();
        // coalesced relu'd cat store
        for (int k = t; k < 2048; k += 512) {
            int c = k >> 6, n = k & 63;
            catw[i * 2048 + k] = fmaxf(sT[c * 66 + n], 0.f);
        }
    }
}

// ---------------- projection (8o x 8n register tiles) + inverse WT ----------
#define PW_STRIDE 260
#define PA_OFF 8320                  // s_act [32][68]
#define PA_STRIDE 68
#define PE_OFF 0                     // epilogue subband stage [3][32][64]
#define PT_OFF 6144                  // epilogue proj stage [32][66]
#define PROJ_SMEM_FLOATS 10496
#define PROJ_SMEM_BYTES (PROJ_SMEM_FLOATS * 4)

__global__ __launch_bounds__(256, 2)
void wwa_proj(const float* __restrict__ pbias, const float* __restrict__ iwt,
              float* __restrict__ out) {
    extern __shared__ float sm[];
    const int t = threadIdx.x, w = blockIdx.x;
    const int b = w >> 8, wy = (w >> 4) & 15, wx = w & 15;
    const int tx = t & 7, ty = t >> 3;
    const int o0 = ty * 8, n0 = tx * 8;
    const float* catw = g_cat + (size_t)w * 16384;

    u64 acc[8][4];
#pragma unroll
    for (int oi = 0; oi < 8; oi++) {
        float pv = pbias[o0 + oi];
        u64 pi = pack2(pv, pv);
#pragma unroll
        for (int np = 0; np < 4; np++) acc[oi][np] = pi;
    }

#pragma unroll 1
    for (int cc = 0; cc < 8; cc++) {
        __syncthreads();
        const float4* wsrc = (const float4*)(g_pwT + cc * 32 * 256);
        for (int k = t; k < 2048; k += 256) {
            int ci = k >> 6, o4 = k & 63;
            *(float4*)&sm[ci * PW_STRIDE + o4 * 4] = wsrc[k];
        }
        const float4* asrc = (const float4*)(catw + cc * 2048);
        for (int k = t; k < 512; k += 256) {
            int ci = k >> 4, n4 = k & 15;
            *(float4*)&sm[PA_OFF + ci * PA_STRIDE + n4 * 4] = asrc[k];
        }
        __syncthreads();
#pragma unroll 4
        for (int c = 0; c < 32; c++) {
            float4 wa = *(const float4*)&sm[c * PW_STRIDE + o0];
            float4 wb = *(const float4*)&sm[c * PW_STRIDE + o0 + 4];
            longlong2 p0 = *(const longlong2*)&sm[PA_OFF + c * PA_STRIDE + n0];
            longlong2 p1 = *(const longlong2*)&sm[PA_OFF + c * PA_STRIDE + n0 + 4];
            u64 av0 = (u64)p0.x, av1 = (u64)p0.y, av2 = (u64)p1.x, av3 = (u64)p1.y;
            u64 wv[8];
            wv[0] = pack2(wa.x, wa.x); wv[1] = pack2(wa.y, wa.y);
            wv[2] = pack2(wa.z, wa.z); wv[3] = pack2(wa.w, wa.w);
            wv[4] = pack2(wb.x, wb.x); wv[5] = pack2(wb.y, wb.y);
            wv[6] = pack2(wb.z, wb.z); wv[7] = pack2(wb.w, wb.w);
#pragma unroll
            for (int oi = 0; oi < 8; oi++) {
                fma2(acc[oi][0], wv[oi], av0);
                fma2(acc[oi][1], wv[oi], av1);
                fma2(acc[oi][2], wv[oi], av2);
                fma2(acc[oi][3], wv[oi], av3);
            }
        }
    }

    // ---- epilogue: inverse WT, per 32-o block ----
    const float* subw1 = g_sub + ((size_t)BN + w) * 16384;
    const float* subw2 = g_sub + ((size_t)2 * BN + w) * 16384;
    const float* subw3 = g_sub + ((size_t)3 * BN + w) * 16384;
    float* ob = out + (size_t)b * DIM * RES * RES + (size_t)(wy * 16) * RES + wx * 16;
    const int en = t & 63, eg = t >> 6;       // pixel n, oo-group
    const int py = en >> 3, qx = en & 7;
    const float4* iw4 = (const float4*)iwt;

#pragma unroll 1
    for (int obk = 0; obk < 8; obk++) {
        __syncthreads();
        for (int k = t; k < 1536; k += 256) {
            int arr = k >> 9, r = k & 511;
            const float* src = arr == 0 ? subw1 : arr == 1 ? subw2 : subw3;
            *(float4*)&sm[PE_OFF + arr * 2048 + r * 4] =
                *(const float4*)&src[obk * 2048 + r * 4];
        }
        if ((ty >> 2) == obk) {
            int ol = (ty & 3) * 8;
#pragma unroll
            for (int oi = 0; oi < 8; oi++)
#pragma unroll
                for (int np = 0; np < 4; np++) {
                    float lo, hi; unpack2(acc[oi][np], lo, hi);
                    *(float2*)&sm[PT_OFF + (ol + oi) * 66 + n0 + np * 2] = make_float2(lo, hi);
                }
        }
        __syncthreads();
#pragma unroll 1
        for (int oj = 0; oj < 8; oj++) {
            int oo = eg * 8 + oj;
            int o = obk * 32 + oo;
            float a  = sm[PT_OFF + oo * 66 + en];
            float lh = sm[PE_OFF + oo * 64 + en];
            float hl = sm[PE_OFF + 2048 + oo * 64 + en];
            float hh = sm[PE_OFF + 4096 + oo * 64 + en];
            float4 f0 = iw4[4 * o + 0], f1 = iw4[4 * o + 1];
            float4 f2 = iw4[4 * o + 2], f3 = iw4[4 * o + 3];
            float r00 = a * f0.x + lh * f1.x + hl * f2.x + hh * f3.x;
            float r01 = a * f0.y + lh * f1.y + hl * f2.y + hh * f3.y;
            float r10 = a * f0.z + lh * f1.z + hl * f2.z + hh * f3.z;
            float r11 = a * f0.w + lh * f1.w + hl * f2.w + hh * f3.w;
            float* po = ob + (size_t)o * (RES * RES) + (2 * py) * RES + 2 * qx;
            *(float2*)po = make_float2(r00, r01);
            *(float2*)(po + RES) = make_float2(r10, r11);
        }
    }
}

extern "C" void kernel_launch(void* const* d_in, const int* in_sizes, int n_in,
                              void* d_out, int out_size) {
    const float* x    = (const float*)d_in[0];
    const float* wtf  = (const float*)d_in[1];
    const float* iwtf = (const float*)d_in[2];
    const float* dww  = (const float*)d_in[3];
    const float* dwb  = (const float*)d_in[4];
    const float* pw   = (const float*)d_in[5];
    const float* pb   = (const float*)d_in[6];
    const float* ab   = (const float*)d_in[7];
    const int*   idxs = (const int*)d_in[8];
    int n_off = in_sizes[7] / HEADS;
    float* out = (float*)d_out;

    wwa_bias<<<128, 256>>>(ab, idxs, n_off);
    wwa_pwT<<<64, 256>>>(pw);
    wwa_wt<<<16384, 256>>>(x, wtf);
    wwa_attn<<<BN * HEADS, 256>>>(dww, dwb);
    wwa_casc<<<BN, 512>>>();
    wwa_proj<<<BN, 256, PROJ_SMEM_BYTES>>>(pb, iwtf, out);
}

// round 8
// speedup vs baseline: 1.2436x; 1.2436x over previous
#include <cuda_runtime.h>

#define BATCH 2
#define DIM   256
#define HEADS 8
#define HD    32
#define RES   256
#define FWS   8
#define BN    512            // BATCH * 16 * 16 windows
#define NPIX  64
#define ATTN_SCALE 0.17677669529663689f

// ---------------- device scratch ----------------
__device__ float g_sub[(size_t)4 * BN * DIM * NPIX];          // [s][w][c][n]  134.2 MB
__device__ float g_bias[HEADS * NPIX * NPIX];                 // 128 KB
__device__ float g_attn[(size_t)BN * HEADS * NPIX * NPIX];    // softmaxed attn, 67 MB

typedef unsigned long long u64;

__device__ __forceinline__ u64 pack2(float lo, float hi) {
    u64 r; asm("mov.b64 %0,{%1,%2};" : "=l"(r) : "f"(lo), "f"(hi)); return r;
}
__device__ __forceinline__ void unpack2(u64 v, float& a, float& b) {
    asm("mov.b64 {%0,%1},%2;" : "=f"(a), "=f"(b) : "l"(v));
}
__device__ __forceinline__ void fma2(u64& d, u64 a, u64 b) {
    asm("fma.rn.f32x2 %0,%1,%2,%0;" : "+l"(d) : "l"(a), "l"(b));
}

// ---------------- bias gather ----------------
__global__ void wwa_bias(const float* __restrict__ ab, const int* __restrict__ idxs, int n_off) {
    int idx = blockIdx.x * 256 + threadIdx.x;
    int i = idx >> 12, r = idx & 4095;
    g_bias[idx] = ab[i * n_off + idxs[r]];
}

// ---------------- wavelet transform ----------------
__global__ void wwa_wt(const float* __restrict__ x, const float* __restrict__ wf) {
    int g = blockIdx.x * 256 + threadIdx.x;
    int pair = g & 31;
    int c = (g >> 5) & 255;
    int w = g >> 13;
    int b = w >> 8, wy = (w >> 4) & 15, wx = w & 15;
    int n0 = pair * 2;
    int p = wy * 8 + (n0 >> 3);
    int q0 = wx * 8 + (n0 & 7);
    const float* xp = x + ((size_t)(b * DIM + c) * RES + 2 * p) * RES + 2 * q0;
    float4 r0 = *(const float4*)xp;
    float4 r1 = *(const float4*)(xp + RES);
    const float4* wf4 = (const float4*)wf;
    float* dst = g_sub + ((size_t)w * DIM + c) * NPIX + n0;
#pragma unroll
    for (int s = 0; s < 4; s++) {
        float4 f = wf4[4 * c + s];
        float o0 = r0.x * f.x + r0.y * f.y + r1.x * f.z + r1.y * f.w;
        float o1 = r0.z * f.x + r0.w * f.y + r1.z * f.z + r1.w * f.w;
        *(float2*)(dst + (size_t)s * BN * DIM * NPIX) = make_float2(o0, o1);
    }
}

// ---------------- attention precompute: conv -> QK^T -> softmax -> g_attn ----
// one CTA per (window, head); 4096 CTAs, dynamic smem 54528 B
#define A_T   0
#define A_DWW 6272
#define A_DWB 7072
#define A_Q   7104
#define A_K   11456
#define A_TOT 13632
#define ATTN_SMEM_BYTES (A_TOT * 4)

__global__ __launch_bounds__(256)
void wwa_attn(const float* __restrict__ dww, const float* __restrict__ dwb) {
    extern __shared__ float sm[];
    const int t = threadIdx.x;
    const int wh = blockIdx.x;
    const int w = wh >> 3, i = wh & 7;
    const float4* lhp4 = (const float4*)(g_sub + ((size_t)BN + w) * 16384 + i * 2048);
    const float4* hlp4 = (const float4*)(g_sub + ((size_t)2 * BN + w) * 16384 + i * 2048);

    // zero conv tile (halo must be 0)
    for (int k = t; k < 1568; k += 256)
        ((float4*)sm)[k] = make_float4(0.f, 0.f, 0.f, 0.f);
    __syncthreads();
    // stage lh into padded conv tile, hl into k
    for (int k = t; k < 512; k += 256) {
        float4 v = lhp4[k];
        int c = k >> 4, n0 = (k & 15) * 4;
        int off = A_T + c * 196 + ((n0 >> 3) + 2) * 16 + (n0 & 7) + 2;
        *(float2*)&sm[off]     = make_float2(v.x, v.y);
        *(float2*)&sm[off + 2] = make_float2(v.z, v.w);
        float4 u = hlp4[k];
        *(float4*)&sm[A_K + c * 68 + n0] = u;
    }
    for (int k = t; k < 800; k += 256) sm[A_DWW + k] = dww[i * 800 + k];
    if (t < 32) sm[A_DWB + t] = dwb[i * 32 + t];
    __syncthreads();

    // depthwise 5x5 conv (pad 2): thread (d, py) -> 8 outputs, register-blocked rows
    {
        const int d = t & 31, py = t >> 5;
        float acc[8];
        float bb = sm[A_DWB + d];
#pragma unroll
        for (int qx = 0; qx < 8; qx++) acc[qx] = bb;
        const float* wp = &sm[A_DWW + d * 25];
        const float* tp = &sm[A_T + d * 196 + py * 16];
#pragma unroll
        for (int ii = 0; ii < 5; ii++) {
            float4 ra = *(const float4*)&tp[ii * 16];
            float4 rb = *(const float4*)&tp[ii * 16 + 4];
            float4 rc = *(const float4*)&tp[ii * 16 + 8];
            float row[12] = {ra.x, ra.y, ra.z, ra.w,
                             rb.x, rb.y, rb.z, rb.w,
                             rc.x, rc.y, rc.z, rc.w};
#pragma unroll
            for (int jj = 0; jj < 5; jj++) {
                float wv = wp[ii * 5 + jj];
#pragma unroll
                for (int qx = 0; qx < 8; qx++)
                    acc[qx] += row[qx + jj] * wv;
            }
        }
#pragma unroll
        for (int qx = 0; qx < 8; qx++) {
            int n = py * 8 + qx;
            *(u64*)&sm[A_Q + n * 68 + 2 * d] = pack2(acc[qx], acc[qx]);
        }
    }
    __syncthreads();

    // attn = softmax(q k^T * scale + bias) -> global
    {
        const int rg = t >> 4, cg = t & 15, m0 = cg * 4;
        u64 acc[4][2] = {};
#pragma unroll 4
        for (int d = 0; d < 32; d += 2) {
            longlong2 ka = *(const longlong2*)&sm[A_K + d * 68 + m0];
            longlong2 kb = *(const longlong2*)&sm[A_K + (d + 1) * 68 + m0];
#pragma unroll
            for (int r = 0; r < 4; r++) {
                longlong2 q2 = *(const longlong2*)&sm[A_Q + (rg * 4 + r) * 68 + 2 * d];
                fma2(acc[r][0], (u64)q2.x, (u64)ka.x);
                fma2(acc[r][1], (u64)q2.x, (u64)ka.y);
                fma2(acc[r][0], (u64)q2.y, (u64)kb.x);
                fma2(acc[r][1], (u64)q2.y, (u64)kb.y);
            }
        }
        float* ap = g_attn + (size_t)wh * 4096;
#pragma unroll
        for (int r = 0; r < 4; r++) {
            int n = rg * 4 + r;
            float v0, v1, v2, v3;
            unpack2(acc[r][0], v0, v1);
            unpack2(acc[r][1], v2, v3);
            const float4 bv = *(const float4*)&g_bias[i * 4096 + n * 64 + m0];
            v0 = v0 * ATTN_SCALE + bv.x; v1 = v1 * ATTN_SCALE + bv.y;
            v2 = v2 * ATTN_SCALE + bv.z; v3 = v3 * ATTN_SCALE + bv.w;
            float mx = fmaxf(fmaxf(v0, v1), fmaxf(v2, v3));
#pragma unroll
            for (int off = 8; off >= 1; off >>= 1)
                mx = fmaxf(mx, __shfl_xor_sync(0xffffffffu, mx, off));
            v0 = __expf(v0 - mx); v1 = __expf(v1 - mx);
            v2 = __expf(v2 - mx); v3 = __expf(v3 - mx);
            float s = v0 + v1 + v2 + v3;
#pragma unroll
            for (int off = 8; off >= 1; off >>= 1)
                s += __shfl_xor_sync(0xffffffffu, s, off);
            float inv = __fdividef(1.f, s);
            *(float4*)&ap[n * 64 + m0] = make_float4(v0 * inv, v1 * inv, v2 * inv, v3 * inv);
        }
    }
}

// ---------------- cascade + projection + inverse WT (R5 fused version) -------
#define C_OUT 0                      // relu'd cat    [256][68] = 17408
#define C_V   17408                  // running v     [32][66]  =  2112
#define C_TMP 19520                  // raw attn out  [32][66]  =  2112
#define C_ATT 21632                  // attn tile     [64][68]  =  4352
#define C_TOT 25984
#define C_W   17408                  // proj weight chunk [256][33] = 8448 (overlay)
#define C_E   0                      // epilogue subband stage [3][256][9] (overlay)
#define C_SO  6912                   // epilogue out stage [256][33] (overlay)
#define SMEM_BYTES (C_TOT * 4)

__global__ __launch_bounds__(512, 2)
void wwa_casc(const float* __restrict__ pw, const float* __restrict__ pbias,
              const float* __restrict__ iwt, float* __restrict__ out) {
    extern __shared__ float sm[];
    const int t = threadIdx.x;
    const int w = blockIdx.x;
    const int b = w >> 8, wy = (w >> 4) & 15, wx = w & 15;
    const float* subw0 = g_sub + (size_t)w * DIM * NPIX;
    const float* subw1 = g_sub + ((size_t)BN + w) * DIM * NPIX;
    const float* subw2 = g_sub + ((size_t)2 * BN + w) * DIM * NPIX;
    const float* subw3 = g_sub + ((size_t)3 * BN + w) * DIM * NPIX;

#pragma unroll 1
    for (int i = 0; i < 8; i++) {
        __syncthreads();
        const float* ap = g_attn + (size_t)((w << 3) | i) * 4096;
        for (int k = t; k < 4096; k += 512) {
            int n = k >> 6, m = k & 63;
            sm[C_ATT + n * 68 + m] = ap[k];
        }
        const float* llp = subw0 + i * 2048;
        if (i == 0) {
            for (int k = t; k < 2048; k += 512) {
                int c = k >> 6, n = k & 63;
                sm[C_V + c * 66 + n] = llp[k];
            }
        } else {
            for (int k = t; k < 2048; k += 512) {
                int c = k >> 6, n = k & 63;
                sm[C_V + c * 66 + n] = sm[C_TMP + c * 66 + n] + llp[k];
            }
        }
        __syncthreads();

        // out[d][n] = sum_m v[d][m] * attn[n][m]
        int d = t & 31, n0 = (t >> 5) * 4;
        u64 acc[4] = {};
#pragma unroll 4
        for (int m = 0; m < 64; m += 4) {
            u64 v0 = *(const u64*)&sm[C_V + d * 66 + m];
            u64 v1 = *(const u64*)&sm[C_V + d * 66 + m + 2];
#pragma unroll
            for (int j = 0; j < 4; j++) {
                longlong2 a2 = *(const longlong2*)&sm[C_ATT + (n0 + j) * 68 + m];
                fma2(acc[j], v0, (u64)a2.x);
                fma2(acc[j], v1, (u64)a2.y);
            }
        }
#pragma unroll
        for (int j = 0; j < 4; j++) {
            float lo, hi; unpack2(acc[j], lo, hi);
            float val = lo + hi;
            sm[C_TMP + d * 66 + n0 + j] = val;
            sm[C_OUT + (i * 32 + d) * 68 + n0 + j] = fmaxf(val, 0.f);
        }
    }
    __syncthreads();

    // --- projection: o = t&255, half = t>>8 covers 32 pixels (16 u64) ---
    const int o = t & 255, half = t >> 8;
    u64 acc[16];
    {
        float pbv = pbias[o];
        u64 pi = pack2(pbv, pbv);
#pragma unroll
        for (int u = 0; u < 16; u++) acc[u] = pi;
    }
#pragma unroll 1
    for (int cc = 0; cc < 256; cc += 32) {
        __syncthreads();
        for (int k = t; k < 8192; k += 512) {
            int oo = k >> 5, c = k & 31;
            sm[C_W + oo * 33 + c] = pw[oo * 256 + cc + c];
        }
        __syncthreads();
#pragma unroll 4
        for (int c2 = 0; c2 < 32; c2++) {
            float wv = sm[C_W + o * 33 + c2];
            u64 w2 = pack2(wv, wv);
            const longlong2* row = (const longlong2*)&sm[C_OUT + (cc + c2) * 68 + half * 32];
#pragma unroll
            for (int u = 0; u < 8; u++) {
                longlong2 p = row[u];
                fma2(acc[2 * u],     w2, (u64)p.x);
                fma2(acc[2 * u + 1], w2, (u64)p.y);
            }
        }
    }

    // --- inverse WT epilogue, staged for coalescing ---
    const float4* iw4 = (const float4*)iwt;
    float4 f0 = iw4[4 * o + 0], f1 = iw4[4 * o + 1];
    float4 f2 = iw4[4 * o + 2], f3 = iw4[4 * o + 3];
    float* ob = out + (size_t)(b * DIM) * RES * RES;
    const int ybase = wy * 16, xbase = wx * 16;

#pragma unroll 1
    for (int ch = 0; ch < 8; ch++) {
        __syncthreads();
        for (int k = t; k < 6144; k += 512) {
            int arr = k >> 11, r = k & 2047;
            int oo = r >> 3, p = r & 7;
            int hh = p >> 2, pp = p & 3;
            int n = hh * 32 + 4 * ch + pp;
            const float* src = (arr == 0) ? subw1 : (arr == 1) ? subw2 : subw3;
            sm[C_E + arr * 2304 + oo * 9 + p] = src[oo * 64 + n];
        }
        __syncthreads();
        {
            float av[4];
            unpack2(acc[2 * ch],     av[0], av[1]);
            unpack2(acc[2 * ch + 1], av[2], av[3]);
#pragma unroll
            for (int pp = 0; pp < 4; pp++) {
                float a  = av[pp];
                float lh = sm[C_E + 0 * 2304 + o * 9 + half * 4 + pp];
                float hl = sm[C_E + 1 * 2304 + o * 9 + half * 4 + pp];
                float hh = sm[C_E + 2 * 2304 + o * 9 + half * 4 + pp];
                float o00 = a * f0.x + lh * f1.x + hl * f2.x + hh * f3.x;
                float o01 = a * f0.y + lh * f1.y + hl * f2.y + hh * f3.y;
                float o10 = a * f0.z + lh * f1.z + hl * f2.z + hh * f3.z;
                float o11 = a * f0.w + lh * f1.w + hl * f2.w + hh * f3.w;
                int jb = half * 16 + pp * 2;
                sm[C_SO + o * 33 + jb + 0] = o00;
                sm[C_SO + o * 33 + jb + 1] = o01;
                sm[C_SO + o * 33 + jb + 8] = o10;
                sm[C_SO + o * 33 + jb + 9] = o11;
            }
        }
        __syncthreads();
        for (int k = t; k < 8192; k += 512) {
            int oo = k >> 5, j = k & 31;
            int hh = j >> 4, jj = j & 15;
            int py = 4 * hh + (ch >> 1);
            int y = ybase + 2 * py + (jj >> 3);
            int x = xbase + 2 * ((ch & 1) * 4) + (jj & 7);
            ob[(size_t)oo * RES * RES + (size_t)y * RES + x] = sm[C_SO + oo * 33 + hh * 16 + jj];
        }
    }
}

extern "C" void kernel_launch(void* const* d_in, const int* in_sizes, int n_in,
                              void* d_out, int out_size) {
    const float* x    = (const float*)d_in[0];
    const float* wtf  = (const float*)d_in[1];
    const float* iwtf = (const float*)d_in[2];
    const float* dww  = (const float*)d_in[3];
    const float* dwb  = (const float*)d_in[4];
    const float* pw   = (const float*)d_in[5];
    const float* pb   = (const float*)d_in[6];
    const float* ab   = (const float*)d_in[7];
    const int*   idxs = (const int*)d_in[8];
    int n_off = in_sizes[7] / HEADS;
    float* out = (float*)d_out;

    cudaFuncSetAttribute(wwa_attn, cudaFuncAttributeMaxDynamicSharedMemorySize, ATTN_SMEM_BYTES);
    cudaFuncSetAttribute(wwa_casc, cudaFuncAttributeMaxDynamicSharedMemorySize, SMEM_BYTES);

    wwa_bias<<<128, 256>>>(ab, idxs, n_off);
    wwa_wt<<<16384, 256>>>(x, wtf);
    wwa_attn<<<BN * HEADS, 256, ATTN_SMEM_BYTES>>>(dww, dwb);
    wwa_casc<<<BN, 512, SMEM_BYTES>>>(pw, pb, iwtf, out);
}

// round 9
// speedup vs baseline: 1.3962x; 1.1227x over previous
#include <cuda_runtime.h>

#define BATCH 2
#define DIM   256
#define HEADS 8
#define HD    32
#define RES   256
#define FWS   8
#define BN    512            // BATCH * 16 * 16 windows
#define NPIX  64
#define ATTN_SCALE 0.17677669529663689f

// ---------------- device scratch ----------------
__device__ float g_sub[(size_t)4 * BN * DIM * NPIX];          // [s][w][c][n]  134.2 MB
__device__ float g_bias[HEADS * NPIX * NPIX];                 // 128 KB
__device__ float g_attn[(size_t)BN * HEADS * NPIX * NPIX];    // softmaxed attn, 67 MB
__device__ float g_pwT[DIM * DIM];                            // transposed proj weight

typedef unsigned long long u64;

__device__ __forceinline__ u64 pack2(float lo, float hi) {
    u64 r; asm("mov.b64 %0,{%1,%2};" : "=l"(r) : "f"(lo), "f"(hi)); return r;
}
__device__ __forceinline__ void unpack2(u64 v, float& a, float& b) {
    asm("mov.b64 {%0,%1},%2;" : "=f"(a), "=f"(b) : "l"(v));
}
__device__ __forceinline__ void fma2(u64& d, u64 a, u64 b) {
    asm("fma.rn.f32x2 %0,%1,%2,%0;" : "+l"(d) : "l"(a), "l"(b));
}

// ---------------- bias gather ----------------
__global__ void wwa_bias(const float* __restrict__ ab, const int* __restrict__ idxs, int n_off) {
    int idx = blockIdx.x * 256 + threadIdx.x;
    int i = idx >> 12, r = idx & 4095;
    g_bias[idx] = ab[i * n_off + idxs[r]];
}

// ---------------- proj weight transpose: g_pwT[c][o] = pw[o][c] -------------
__global__ void wwa_pwT(const float* __restrict__ pw) {
    __shared__ float tile[32][33];
    int bo = blockIdx.x & 7, bc = blockIdx.x >> 3;
    int lx = threadIdx.x & 31, ly = threadIdx.x >> 5;   // 256 threads: 32x8
    for (int r = ly; r < 32; r += 8)
        tile[r][lx] = pw[(bo * 32 + r) * 256 + bc * 32 + lx];
    __syncthreads();
    for (int r = ly; r < 32; r += 8)
        g_pwT[(bc * 32 + r) * 256 + bo * 32 + lx] = tile[lx][r];
}

// ---------------- wavelet transform ----------------
__global__ void wwa_wt(const float* __restrict__ x, const float* __restrict__ wf) {
    int g = blockIdx.x * 256 + threadIdx.x;
    int pair = g & 31;
    int c = (g >> 5) & 255;
    int w = g >> 13;
    int b = w >> 8, wy = (w >> 4) & 15, wx = w & 15;
    int n0 = pair * 2;
    int p = wy * 8 + (n0 >> 3);
    int q0 = wx * 8 + (n0 & 7);
    const float* xp = x + ((size_t)(b * DIM + c) * RES + 2 * p) * RES + 2 * q0;
    float4 r0 = *(const float4*)xp;
    float4 r1 = *(const float4*)(xp + RES);
    const float4* wf4 = (const float4*)wf;
    float* dst = g_sub + ((size_t)w * DIM + c) * NPIX + n0;
#pragma unroll
    for (int s = 0; s < 4; s++) {
        float4 f = wf4[4 * c + s];
        float o0 = r0.x * f.x + r0.y * f.y + r1.x * f.z + r1.y * f.w;
        float o1 = r0.z * f.x + r0.w * f.y + r1.z * f.z + r1.w * f.w;
        *(float2*)(dst + (size_t)s * BN * DIM * NPIX) = make_float2(o0, o1);
    }
}

// ---------------- attention precompute (unchanged, R8-proven) ----------------
#define A_T   0
#define A_DWW 6272
#define A_DWB 7072
#define A_Q   7104
#define A_K   11456
#define A_TOT 13632
#define ATTN_SMEM_BYTES (A_TOT * 4)

__global__ __launch_bounds__(256)
void wwa_attn(const float* __restrict__ dww, const float* __restrict__ dwb) {
    extern __shared__ float sm[];
    const int t = threadIdx.x;
    const int wh = blockIdx.x;
    const int w = wh >> 3, i = wh & 7;
    const float4* lhp4 = (const float4*)(g_sub + ((size_t)BN + w) * 16384 + i * 2048);
    const float4* hlp4 = (const float4*)(g_sub + ((size_t)2 * BN + w) * 16384 + i * 2048);

    for (int k = t; k < 1568; k += 256)
        ((float4*)sm)[k] = make_float4(0.f, 0.f, 0.f, 0.f);
    __syncthreads();
    for (int k = t; k < 512; k += 256) {
        float4 v = lhp4[k];
        int c = k >> 4, n0 = (k & 15) * 4;
        int off = A_T + c * 196 + ((n0 >> 3) + 2) * 16 + (n0 & 7) + 2;
        *(float2*)&sm[off]     = make_float2(v.x, v.y);
        *(float2*)&sm[off + 2] = make_float2(v.z, v.w);
        float4 u = hlp4[k];
        *(float4*)&sm[A_K + c * 68 + n0] = u;
    }
    for (int k = t; k < 800; k += 256) sm[A_DWW + k] = dww[i * 800 + k];
    if (t < 32) sm[A_DWB + t] = dwb[i * 32 + t];
    __syncthreads();

    {
        const int d = t & 31, py = t >> 5;
        float acc[8];
        float bb = sm[A_DWB + d];
#pragma unroll
        for (int qx = 0; qx < 8; qx++) acc[qx] = bb;
        const float* wp = &sm[A_DWW + d * 25];
        const float* tp = &sm[A_T + d * 196 + py * 16];
#pragma unroll
        for (int ii = 0; ii < 5; ii++) {
            float4 ra = *(const float4*)&tp[ii * 16];
            float4 rb = *(const float4*)&tp[ii * 16 + 4];
            float4 rc = *(const float4*)&tp[ii * 16 + 8];
            float row[12] = {ra.x, ra.y, ra.z, ra.w,
                             rb.x, rb.y, rb.z, rb.w,
                             rc.x, rc.y, rc.z, rc.w};
#pragma unroll
            for (int jj = 0; jj < 5; jj++) {
                float wv = wp[ii * 5 + jj];
#pragma unroll
                for (int qx = 0; qx < 8; qx++)
                    acc[qx] += row[qx + jj] * wv;
            }
        }
#pragma unroll
        for (int qx = 0; qx < 8; qx++) {
            int n = py * 8 + qx;
            *(u64*)&sm[A_Q + n * 68 + 2 * d] = pack2(acc[qx], acc[qx]);
        }
    }
    __syncthreads();

    {
        const int rg = t >> 4, cg = t & 15, m0 = cg * 4;
        u64 acc[4][2] = {};
#pragma unroll 4
        for (int d = 0; d < 32; d += 2) {
            longlong2 ka = *(const longlong2*)&sm[A_K + d * 68 + m0];
            longlong2 kb = *(const longlong2*)&sm[A_K + (d + 1) * 68 + m0];
#pragma unroll
            for (int r = 0; r < 4; r++) {
                longlong2 q2 = *(const longlong2*)&sm[A_Q + (rg * 4 + r) * 68 + 2 * d];
                fma2(acc[r][0], (u64)q2.x, (u64)ka.x);
                fma2(acc[r][1], (u64)q2.x, (u64)ka.y);
                fma2(acc[r][0], (u64)q2.y, (u64)kb.x);
                fma2(acc[r][1], (u64)q2.y, (u64)kb.y);
            }
        }
        float* ap = g_attn + (size_t)wh * 4096;
#pragma unroll
        for (int r = 0; r < 4; r++) {
            int n = rg * 4 + r;
            float v0, v1, v2, v3;
            unpack2(acc[r][0], v0, v1);
            unpack2(acc[r][1], v2, v3);
            const float4 bv = *(const float4*)&g_bias[i * 4096 + n * 64 + m0];
            v0 = v0 * ATTN_SCALE + bv.x; v1 = v1 * ATTN_SCALE + bv.y;
            v2 = v2 * ATTN_SCALE + bv.z; v3 = v3 * ATTN_SCALE + bv.w;
            float mx = fmaxf(fmaxf(v0, v1), fmaxf(v2, v3));
#pragma unroll
            for (int off = 8; off >= 1; off >>= 1)
                mx = fmaxf(mx, __shfl_xor_sync(0xffffffffu, mx, off));
            v0 = __expf(v0 - mx); v1 = __expf(v1 - mx);
            v2 = __expf(v2 - mx); v3 = __expf(v3 - mx);
            float s = v0 + v1 + v2 + v3;
#pragma unroll
            for (int off = 8; off >= 1; off >>= 1)
                s += __shfl_xor_sync(0xffffffffu, s, off);
            float inv = __fdividef(1.f, s);
            *(float4*)&ap[n * 64 + m0] = make_float4(v0 * inv, v1 * inv, v2 * inv, v3 * inv);
        }
    }
}

// ---------------- cascade + projection + inverse WT (v3) ---------------------
// smem float offsets:
//   C_OUT [256][68] = 17408   relu'd cat; later reused to hold proj results P
//   region at 17408, overlaid:
//     phase1: C_V [32][68]=2176, C_TMP [32][68]=2176, C_ATT [64][64]=4096
//     phase3: C_E  [3][32][68]=6528
#define C_OUT 0
#define C_V   17408
#define C_TMP 19584
#define C_ATT 21760
#define C_E   17408
#define SMEM_FLOATS 25856
#define SMEM_BYTES  (SMEM_FLOATS * 4)

__global__ __launch_bounds__(512, 2)
void wwa_casc(const float* __restrict__ pbias, const float* __restrict__ iwt,
              float* __restrict__ out) {
    extern __shared__ float sm[];
    const int t = threadIdx.x;
    const int w = blockIdx.x;
    const int b = w >> 8, wy = (w >> 4) & 15, wx = w & 15;
    const float* subw0 = g_sub + (size_t)w * 16384;
    const float* subw1 = g_sub + ((size_t)BN + w) * 16384;
    const float* subw2 = g_sub + ((size_t)2 * BN + w) * 16384;
    const float* subw3 = g_sub + ((size_t)3 * BN + w) * 16384;

    // ============ phase 1: cascade AV ============
#pragma unroll 1
    for (int i = 0; i < 8; i++) {
        __syncthreads();
        // attn tile: packed [64][64] -> contiguous float4 copy (2 per thread)
        const float4* ap4 = (const float4*)(g_attn + (size_t)((w << 3) | i) * 4096);
        float4* sa4 = (float4*)&sm[C_ATT];
#pragma unroll
        for (int k = t; k < 1024; k += 512) sa4[k] = ap4[k];
        // v update (1 float4 per thread)
        const float4* llp4 = (const float4*)(subw0 + i * 2048);
        {
            int k = t;  // 512 float4s exactly
            int c = k >> 4, m4 = (k & 15) * 4;
            float4 l4 = llp4[k];
            if (i > 0) {
                float4 t4 = *(const float4*)&sm[C_TMP + c * 68 + m4];
                l4.x += t4.x; l4.y += t4.y; l4.z += t4.z; l4.w += t4.w;
            }
            *(float4*)&sm[C_V + c * 68 + m4] = l4;
        }
        __syncthreads();

        // out[d][n] = sum_m v[d][m] * attn[n][m]
        const int d = t & 31, n0 = (t >> 5) * 4;
        u64 acc[4] = {};
#pragma unroll
        for (int m = 0; m < 64; m += 8) {
            longlong2 va = *(const longlong2*)&sm[C_V + d * 68 + m];
            longlong2 vb = *(const longlong2*)&sm[C_V + d * 68 + m + 4];
#pragma unroll
            for (int j = 0; j < 4; j++) {
                const longlong2* arow = (const longlong2*)&sm[C_ATT + (n0 + j) * 64 + m];
                longlong2 a0 = arow[0], a1 = arow[1];
                fma2(acc[j], (u64)va.x, (u64)a0.x);
                fma2(acc[j], (u64)va.y, (u64)a0.y);
                fma2(acc[j], (u64)vb.x, (u64)a1.x);
                fma2(acc[j], (u64)vb.y, (u64)a1.y);
            }
        }
        float v0l, v0h, v1l, v1h, v2l, v2h, v3l, v3h;
        unpack2(acc[0], v0l, v0h); unpack2(acc[1], v1l, v1h);
        unpack2(acc[2], v2l, v2h); unpack2(acc[3], v3l, v3h);
        float4 raw = make_float4(v0l + v0h, v1l + v1h, v2l + v2h, v3l + v3h);
        *(float4*)&sm[C_TMP + d * 68 + n0] = raw;
        *(float4*)&sm[C_OUT + (i * 32 + d) * 68 + n0] =
            make_float4(fmaxf(raw.x, 0.f), fmaxf(raw.y, 0.f),
                        fmaxf(raw.z, 0.f), fmaxf(raw.w, 0.f));
    }
    __syncthreads();

    // ============ phase 2: projection (weights via coalesced __ldg) ============
    const int o = t & 255, half = t >> 8;
    u64 acc[16];
    {
        float pbv = pbias[o];
        u64 pi = pack2(pbv, pbv);
#pragma unroll
        for (int u = 0; u < 16; u++) acc[u] = pi;
    }
#pragma unroll 4
    for (int c = 0; c < 256; c++) {
        float wv = __ldg(&g_pwT[c * 256 + o]);
        u64 w2 = pack2(wv, wv);
        const longlong2* row = (const longlong2*)&sm[C_OUT + c * 68 + half * 32];
#pragma unroll
        for (int u = 0; u < 8; u++) {
            longlong2 p = row[u];
            fma2(acc[2 * u],     w2, (u64)p.x);
            fma2(acc[2 * u + 1], w2, (u64)p.y);
        }
    }
    __syncthreads();   // all cat reads done; C_OUT becomes P
#pragma unroll
    for (int u = 0; u < 8; u++) {
        longlong2 p;
        p.x = (long long)acc[2 * u];
        p.y = (long long)acc[2 * u + 1];
        *(longlong2*)&sm[C_OUT + o * 68 + half * 32 + u * 4] = p;
    }

    // ============ phase 3: inverse WT epilogue ============
    const int oo = t >> 4, m = t & 15;        // oo 0..31, output row m 0..15
    const int py = m >> 1, ry = m & 1;
    float* obase = out + (size_t)(b * DIM) * RES * RES
                 + (size_t)(wy * 16 + m) * RES + wx * 16;

#pragma unroll 1
    for (int obk = 0; obk < 8; obk++) {
        __syncthreads();   // P visible (first iter) / previous C_E reads done
        // stage subbands [3][32][68] for this 32-o block (3 float4 per thread)
#pragma unroll
        for (int k = t; k < 1536; k += 512) {
            int arr = k >> 9, r = k & 511;
            int o2 = r >> 4, n4 = (r & 15) * 4;
            const float* src = (arr == 0) ? subw1 : (arr == 1) ? subw2 : subw3;
            *(float4*)&sm[C_E + arr * 2176 + o2 * 68 + n4] =
                *(const float4*)&src[obk * 2048 + o2 * 64 + n4];
        }
        __syncthreads();

        const int og = obk * 32 + oo;
        const float* iwp = iwt + og * 16 + 2 * ry;
        float c00 = __ldg(iwp + 0),  c01 = __ldg(iwp + 1);
        float c10 = __ldg(iwp + 4),  c11 = __ldg(iwp + 5);
        float c20 = __ldg(iwp + 8),  c21 = __ldg(iwp + 9);
        float c30 = __ldg(iwp + 12), c31 = __ldg(iwp + 13);
        float* orow = obase + (size_t)og * (RES * RES);
#pragma unroll
        for (int x4 = 0; x4 < 4; x4++) {
            int n = 8 * py + 2 * x4;
            float2 a  = *(const float2*)&sm[C_OUT + og * 68 + n];
            float2 lh = *(const float2*)&sm[C_E + 0 * 2176 + oo * 68 + n];
            float2 hl = *(const float2*)&sm[C_E + 1 * 2176 + oo * 68 + n];
            float2 hh = *(const float2*)&sm[C_E + 2 * 2176 + oo * 68 + n];
            float4 r;
            r.x = a.x * c00 + lh.x * c10 + hl.x * c20 + hh.x * c30;
            r.y = a.x * c01 + lh.x * c11 + hl.x * c21 + hh.x * c31;
            r.z = a.y * c00 + lh.y * c10 + hl.y * c20 + hh.y * c30;
            r.w = a.y * c01 + lh.y * c11 + hl.y * c21 + hh.y * c31;
            *(float4*)&orow[4 * x4] = r;
        }
    }
}

extern "C" void kernel_launch(void* const* d_in, const int* in_sizes, int n_in,
                              void* d_out, int out_size) {
    const float* x    = (const float*)d_in[0];
    const float* wtf  = (const float*)d_in[1];
    const float* iwtf = (const float*)d_in[2];
    const float* dww  = (const float*)d_in[3];
    const float* dwb  = (const float*)d_in[4];
    const float* pw   = (const float*)d_in[5];
    const float* pb   = (const float*)d_in[6];
    const float* ab   = (const float*)d_in[7];
    const int*   idxs = (const int*)d_in[8];
    int n_off = in_sizes[7] / HEADS;
    float* out = (float*)d_out;

    cudaFuncSetAttribute(wwa_attn, cudaFuncAttributeMaxDynamicSharedMemorySize, ATTN_SMEM_BYTES);
    cudaFuncSetAttribute(wwa_casc, cudaFuncAttributeMaxDynamicSharedMemorySize, SMEM_BYTES);

    wwa_bias<<<128, 256>>>(ab, idxs, n_off);
    wwa_pwT<<<64, 256>>>(pw);
    wwa_wt<<<16384, 256>>>(x, wtf);
    wwa_attn<<<BN * HEADS, 256, ATTN_SMEM_BYTES>>>(dww, dwb);
    wwa_casc<<<BN, 512, SMEM_BYTES>>>(pb, iwtf, out);
}

// round 10
// speedup vs baseline: 1.5033x; 1.0767x over previous
#include <cuda_runtime.h>

#define BATCH 2
#define DIM   256
#define HEADS 8
#define HD    32
#define RES   256
#define FWS   8
#define BN    512            // BATCH * 16 * 16 windows
#define NPIX  64
#define ATTN_SCALE 0.17677669529663689f

// ---------------- device scratch ----------------
__device__ float g_sub[(size_t)4 * BN * DIM * NPIX];          // [s][w][c][n]  134.2 MB
__device__ float g_bias[HEADS * NPIX * NPIX];                 // 128 KB
__device__ float g_attn[(size_t)BN * HEADS * NPIX * NPIX];    // softmaxed attn, 67 MB
__device__ float g_pwT[DIM * DIM];                            // transposed proj weight

typedef unsigned long long u64;

__device__ __forceinline__ u64 pack2(float lo, float hi) {
    u64 r; asm("mov.b64 %0,{%1,%2};" : "=l"(r) : "f"(lo), "f"(hi)); return r;
}
__device__ __forceinline__ void unpack2(u64 v, float& a, float& b) {
    asm("mov.b64 {%0,%1},%2;" : "=f"(a), "=f"(b) : "l"(v));
}
__device__ __forceinline__ void fma2(u64& d, u64 a, u64 b) {
    asm("fma.rn.f32x2 %0,%1,%2,%0;" : "+l"(d) : "l"(a), "l"(b));
}

// ---------------- bias gather ----------------
__global__ void wwa_bias(const float* __restrict__ ab, const int* __restrict__ idxs, int n_off) {
    int idx = blockIdx.x * 256 + threadIdx.x;
    int i = idx >> 12, r = idx & 4095;
    g_bias[idx] = ab[i * n_off + idxs[r]];
}

// ---------------- proj weight transpose: g_pwT[c][o] = pw[o][c] -------------
__global__ void wwa_pwT(const float* __restrict__ pw) {
    __shared__ float tile[32][33];
    int bo = blockIdx.x & 7, bc = blockIdx.x >> 3;
    int lx = threadIdx.x & 31, ly = threadIdx.x >> 5;   // 256 threads: 32x8
    for (int r = ly; r < 32; r += 8)
        tile[r][lx] = pw[(bo * 32 + r) * 256 + bc * 32 + lx];
    __syncthreads();
    for (int r = ly; r < 32; r += 8)
        g_pwT[(bc * 32 + r) * 256 + bo * 32 + lx] = tile[lx][r];
}

// ---------------- wavelet transform ----------------
__global__ void wwa_wt(const float* __restrict__ x, const float* __restrict__ wf) {
    int g = blockIdx.x * 256 + threadIdx.x;
    int pair = g & 31;
    int c = (g >> 5) & 255;
    int w = g >> 13;
    int b = w >> 8, wy = (w >> 4) & 15, wx = w & 15;
    int n0 = pair * 2;
    int p = wy * 8 + (n0 >> 3);
    int q0 = wx * 8 + (n0 & 7);
    const float* xp = x + ((size_t)(b * DIM + c) * RES + 2 * p) * RES + 2 * q0;
    float4 r0 = *(const float4*)xp;
    float4 r1 = *(const float4*)(xp + RES);
    const float4* wf4 = (const float4*)wf;
    float* dst = g_sub + ((size_t)w * DIM + c) * NPIX + n0;
#pragma unroll
    for (int s = 0; s < 4; s++) {
        float4 f = wf4[4 * c + s];
        float o0 = r0.x * f.x + r0.y * f.y + r1.x * f.z + r1.y * f.w;
        float o1 = r0.z * f.x + r0.w * f.y + r1.z * f.z + r1.w * f.w;
        *(float2*)(dst + (size_t)s * BN * DIM * NPIX) = make_float2(o0, o1);
    }
}

// ---------------- attention precompute (unchanged, R9-proven) ----------------
#define A_T   0
#define A_DWW 6272
#define A_DWB 7072
#define A_Q   7104
#define A_K   11456
#define A_TOT 13632
#define ATTN_SMEM_BYTES (A_TOT * 4)

__global__ __launch_bounds__(256)
void wwa_attn(const float* __restrict__ dww, const float* __restrict__ dwb) {
    extern __shared__ float sm[];
    const int t = threadIdx.x;
    const int wh = blockIdx.x;
    const int w = wh >> 3, i = wh & 7;
    const float4* lhp4 = (const float4*)(g_sub + ((size_t)BN + w) * 16384 + i * 2048);
    const float4* hlp4 = (const float4*)(g_sub + ((size_t)2 * BN + w) * 16384 + i * 2048);

    for (int k = t; k < 1568; k += 256)
        ((float4*)sm)[k] = make_float4(0.f, 0.f, 0.f, 0.f);
    __syncthreads();
    for (int k = t; k < 512; k += 256) {
        float4 v = lhp4[k];
        int c = k >> 4, n0 = (k & 15) * 4;
        int off = A_T + c * 196 + ((n0 >> 3) + 2) * 16 + (n0 & 7) + 2;
        *(float2*)&sm[off]     = make_float2(v.x, v.y);
        *(float2*)&sm[off + 2] = make_float2(v.z, v.w);
        float4 u = hlp4[k];
        *(float4*)&sm[A_K + c * 68 + n0] = u;
    }
    for (int k = t; k < 800; k += 256) sm[A_DWW + k] = dww[i * 800 + k];
    if (t < 32) sm[A_DWB + t] = dwb[i * 32 + t];
    __syncthreads();

    {
        const int d = t & 31, py = t >> 5;
        float acc[8];
        float bb = sm[A_DWB + d];
#pragma unroll
        for (int qx = 0; qx < 8; qx++) acc[qx] = bb;
        const float* wp = &sm[A_DWW + d * 25];
        const float* tp = &sm[A_T + d * 196 + py * 16];
#pragma unroll
        for (int ii = 0; ii < 5; ii++) {
            float4 ra = *(const float4*)&tp[ii * 16];
            float4 rb = *(const float4*)&tp[ii * 16 + 4];
            float4 rc = *(const float4*)&tp[ii * 16 + 8];
            float row[12] = {ra.x, ra.y, ra.z, ra.w,
                             rb.x, rb.y, rb.z, rb.w,
                             rc.x, rc.y, rc.z, rc.w};
#pragma unroll
            for (int jj = 0; jj < 5; jj++) {
                float wv = wp[ii * 5 + jj];
#pragma unroll
                for (int qx = 0; qx < 8; qx++)
                    acc[qx] += row[qx + jj] * wv;
            }
        }
#pragma unroll
        for (int qx = 0; qx < 8; qx++) {
            int n = py * 8 + qx;
            *(u64*)&sm[A_Q + n * 68 + 2 * d] = pack2(acc[qx], acc[qx]);
        }
    }
    __syncthreads();

    {
        const int rg = t >> 4, cg = t & 15, m0 = cg * 4;
        u64 acc[4][2] = {};
#pragma unroll 4
        for (int d = 0; d < 32; d += 2) {
            longlong2 ka = *(const longlong2*)&sm[A_K + d * 68 + m0];
            longlong2 kb = *(const longlong2*)&sm[A_K + (d + 1) * 68 + m0];
#pragma unroll
            for (int r = 0; r < 4; r++) {
                longlong2 q2 = *(const longlong2*)&sm[A_Q + (rg * 4 + r) * 68 + 2 * d];
                fma2(acc[r][0], (u64)q2.x, (u64)ka.x);
                fma2(acc[r][1], (u64)q2.x, (u64)ka.y);
                fma2(acc[r][0], (u64)q2.y, (u64)kb.x);
                fma2(acc[r][1], (u64)q2.y, (u64)kb.y);
            }
        }
        float* ap = g_attn + (size_t)wh * 4096;
#pragma unroll
        for (int r = 0; r < 4; r++) {
            int n = rg * 4 + r;
            float v0, v1, v2, v3;
            unpack2(acc[r][0], v0, v1);
            unpack2(acc[r][1], v2, v3);
            const float4 bv = *(const float4*)&g_bias[i * 4096 + n * 64 + m0];
            v0 = v0 * ATTN_SCALE + bv.x; v1 = v1 * ATTN_SCALE + bv.y;
            v2 = v2 * ATTN_SCALE + bv.z; v3 = v3 * ATTN_SCALE + bv.w;
            float mx = fmaxf(fmaxf(v0, v1), fmaxf(v2, v3));
#pragma unroll
            for (int off = 8; off >= 1; off >>= 1)
                mx = fmaxf(mx, __shfl_xor_sync(0xffffffffu, mx, off));
            v0 = __expf(v0 - mx); v1 = __expf(v1 - mx);
            v2 = __expf(v2 - mx); v3 = __expf(v3 - mx);
            float s = v0 + v1 + v2 + v3;
#pragma unroll
            for (int off = 8; off >= 1; off >>= 1)
                s += __shfl_xor_sync(0xffffffffu, s, off);
            float inv = __fdividef(1.f, s);
            *(float4*)&ap[n * 64 + m0] = make_float4(v0 * inv, v1 * inv, v2 * inv, v3 * inv);
        }
    }
}

// ---------------- cascade + projection + inverse WT (v4) ---------------------
// smem float offsets:
//   C_OUT [256][68] = 17408   relu'd cat; later reused to hold proj results P
//   C_V   [32][68]  =  2176
//   C_TMP [32][68]  =  2176
//   C_ATT [64][64]  =  4096
#define C_OUT 0
#define C_V   17408
#define C_TMP 19584
#define C_ATT 21760
#define SMEM_FLOATS 25856
#define SMEM_BYTES  (SMEM_FLOATS * 4)

__global__ __launch_bounds__(512, 2)
void wwa_casc(const float* __restrict__ pbias, const float* __restrict__ iwt,
              float* __restrict__ out) {
    extern __shared__ float sm[];
    const int t = threadIdx.x;
    const int w = blockIdx.x;
    const int b = w >> 8, wy = (w >> 4) & 15, wx = w & 15;
    const float* subw0 = g_sub + (size_t)w * 16384;
    const float* subw1 = g_sub + ((size_t)BN + w) * 16384;
    const float* subw2 = g_sub + ((size_t)2 * BN + w) * 16384;
    const float* subw3 = g_sub + ((size_t)3 * BN + w) * 16384;

    // ============ phase 1: cascade AV (software-pipelined) ============
    const float4* llp4 = (const float4*)subw0;               // 512 float4 per head slice
    const float4* atp4 = (const float4*)(g_attn + (size_t)(w << 3) * 4096);
    const int vc = t >> 4, vm4 = (t & 15) * 4;               // this thread's V float4 slot

    // prefetch head 0
    float4 llreg = llp4[t];
    float4 at0 = atp4[t];
    float4 at1 = atp4[t + 512];

#pragma unroll 1
    for (int i = 0; i < 8; i++) {
        __syncthreads();   // prev AV readers done (C_ATT/C_V free), C_TMP ready
        // store staged attn tile + V update
        ((float4*)&sm[C_ATT])[t]       = at0;
        ((float4*)&sm[C_ATT])[t + 512] = at1;
        float4 l4 = llreg;
        if (i > 0) {
            float4 t4 = *(const float4*)&sm[C_TMP + vc * 68 + vm4];
            l4.x += t4.x; l4.y += t4.y; l4.z += t4.z; l4.w += t4.w;
        }
        *(float4*)&sm[C_V + vc * 68 + vm4] = l4;
        __syncthreads();
        // prefetch next head while computing this one
        if (i < 7) {
            llreg = llp4[(i + 1) * 512 + t];
            at0 = atp4[(i + 1) * 1024 + t];
            at1 = atp4[(i + 1) * 1024 + t + 512];
        }

        // out[d][n] = sum_m v[d][m] * attn[n][m]
        const int d = t & 31, n0 = (t >> 5) * 4;
        u64 acc[4] = {};
#pragma unroll
        for (int m = 0; m < 64; m += 8) {
            longlong2 va = *(const longlong2*)&sm[C_V + d * 68 + m];
            longlong2 vb = *(const longlong2*)&sm[C_V + d * 68 + m + 4];
#pragma unroll
            for (int j = 0; j < 4; j++) {
                const longlong2* arow = (const longlong2*)&sm[C_ATT + (n0 + j) * 64 + m];
                longlong2 a0 = arow[0], a1 = arow[1];
                fma2(acc[j], (u64)va.x, (u64)a0.x);
                fma2(acc[j], (u64)va.y, (u64)a0.y);
                fma2(acc[j], (u64)vb.x, (u64)a1.x);
                fma2(acc[j], (u64)vb.y, (u64)a1.y);
            }
        }
        float v0l, v0h, v1l, v1h, v2l, v2h, v3l, v3h;
        unpack2(acc[0], v0l, v0h); unpack2(acc[1], v1l, v1h);
        unpack2(acc[2], v2l, v2h); unpack2(acc[3], v3l, v3h);
        float4 raw = make_float4(v0l + v0h, v1l + v1h, v2l + v2h, v3l + v3h);
        *(float4*)&sm[C_TMP + d * 68 + n0] = raw;
        *(float4*)&sm[C_OUT + (i * 32 + d) * 68 + n0] =
            make_float4(fmaxf(raw.x, 0.f), fmaxf(raw.y, 0.f),
                        fmaxf(raw.z, 0.f), fmaxf(raw.w, 0.f));
    }
    __syncthreads();

    // ============ phase 2: projection (weights via coalesced __ldg) ============
    const int o = t & 255, half = t >> 8;
    u64 acc[16];
    {
        float pbv = pbias[o];
        u64 pi = pack2(pbv, pbv);
#pragma unroll
        for (int u = 0; u < 16; u++) acc[u] = pi;
    }
#pragma unroll 4
    for (int c = 0; c < 256; c++) {
        float wv = __ldg(&g_pwT[c * 256 + o]);
        u64 w2 = pack2(wv, wv);
        const longlong2* row = (const longlong2*)&sm[C_OUT + c * 68 + half * 32];
#pragma unroll
        for (int u = 0; u < 8; u++) {
            longlong2 p = row[u];
            fma2(acc[2 * u],     w2, (u64)p.x);
            fma2(acc[2 * u + 1], w2, (u64)p.y);
        }
    }
    __syncthreads();   // all cat reads done; C_OUT becomes P
#pragma unroll
    for (int u = 0; u < 8; u++) {
        longlong2 p;
        p.x = (long long)acc[2 * u];
        p.y = (long long)acc[2 * u + 1];
        *(longlong2*)&sm[C_OUT + o * 68 + half * 32 + u * 4] = p;
    }
    __syncthreads();   // P visible to all

    // ============ phase 3: inverse WT epilogue (barrier-free, direct LDG) ======
    const int oo = t >> 4, m = t & 15;        // oo 0..31, output row m 0..15
    const int py = m >> 1, ry = m & 1;        // source pixel row, sub-row
    float* obase = out + (size_t)(b * DIM) * RES * RES
                 + (size_t)(wy * 16 + m) * RES + wx * 16;

#pragma unroll 1
    for (int obk = 0; obk < 8; obk++) {
        const int og = obk * 32 + oo;
        const float* iwp = iwt + og * 16 + 2 * ry;
        float c00 = __ldg(iwp + 0),  c01 = __ldg(iwp + 1);
        float c10 = __ldg(iwp + 4),  c11 = __ldg(iwp + 5);
        float c20 = __ldg(iwp + 8),  c21 = __ldg(iwp + 9);
        float c30 = __ldg(iwp + 12), c31 = __ldg(iwp + 13);
        const int nb = og * 64 + 8 * py;
        float4 lhA = __ldg((const float4*)(subw1 + nb));
        float4 lhB = __ldg((const float4*)(subw1 + nb + 4));
        float4 hlA = __ldg((const float4*)(subw2 + nb));
        float4 hlB = __ldg((const float4*)(subw2 + nb + 4));
        float4 hhA = __ldg((const float4*)(subw3 + nb));
        float4 hhB = __ldg((const float4*)(subw3 + nb + 4));
        float4 pA = *(const float4*)&sm[C_OUT + og * 68 + 8 * py];
        float4 pB = *(const float4*)&sm[C_OUT + og * 68 + 8 * py + 4];
        float* orow = obase + (size_t)og * (RES * RES);

        float4 r0, r1, r2, r3;
        r0.x = pA.x * c00 + lhA.x * c10 + hlA.x * c20 + hhA.x * c30;
        r0.y = pA.x * c01 + lhA.x * c11 + hlA.x * c21 + hhA.x * c31;
        r0.z = pA.y * c00 + lhA.y * c10 + hlA.y * c20 + hhA.y * c30;
        r0.w = pA.y * c01 + lhA.y * c11 + hlA.y * c21 + hhA.y * c31;
        r1.x = pA.z * c00 + lhA.z * c10 + hlA.z * c20 + hhA.z * c30;
        r1.y = pA.z * c01 + lhA.z * c11 + hlA.z * c21 + hhA.z * c31;
        r1.z = pA.w * c00 + lhA.w * c10 + hlA.w * c20 + hhA.w * c30;
        r1.w = pA.w * c01 + lhA.w * c11 + hlA.w * c21 + hhA.w * c31;
        r2.x = pB.x * c00 + lhB.x * c10 + hlB.x * c20 + hhB.x * c30;
        r2.y = pB.x * c01 + lhB.x * c11 + hlB.x * c21 + hhB.x * c31;
        r2.z = pB.y * c00 + lhB.y * c10 + hlB.y * c20 + hhB.y * c30;
        r2.w = pB.y * c01 + lhB.y * c11 + hlB.y * c21 + hhB.y * c31;
        r3.x = pB.z * c00 + lhB.z * c10 + hlB.z * c20 + hhB.z * c30;
        r3.y = pB.z * c01 + lhB.z * c11 + hlB.z * c21 + hhB.z * c31;
        r3.z = pB.w * c00 + lhB.w * c10 + hlB.w * c20 + hhB.w * c30;
        r3.w = pB.w * c01 + lhB.w * c11 + hlB.w * c21 + hhB.w * c31;
        *(float4*)&orow[0]  = r0;
        *(float4*)&orow[4]  = r1;
        *(float4*)&orow[8]  = r2;
        *(float4*)&orow[12] = r3;
    }
}

extern "C" void kernel_launch(void* const* d_in, const int* in_sizes, int n_in,
                              void* d_out, int out_size) {
    const float* x    = (const float*)d_in[0];
    const float* wtf  = (const float*)d_in[1];
    const float* iwtf = (const float*)d_in[2];
    const float* dww  = (const float*)d_in[3];
    const float* dwb  = (const float*)d_in[4];
    const float* pw   = (const float*)d_in[5];
    const float* pb   = (const float*)d_in[6];
    const float* ab   = (const float*)d_in[7];
    const int*   idxs = (const int*)d_in[8];
    int n_off = in_sizes[7] / HEADS;
    float* out = (float*)d_out;

    cudaFuncSetAttribute(wwa_attn, cudaFuncAttributeMaxDynamicSharedMemorySize, ATTN_SMEM_BYTES);
    cudaFuncSetAttribute(wwa_casc, cudaFuncAttributeMaxDynamicSharedMemorySize, SMEM_BYTES);

    wwa_bias<<<128, 256>>>(ab, idxs, n_off);
    wwa_pwT<<<64, 256>>>(pw);
    wwa_wt<<<16384, 256>>>(x, wtf);
    wwa_attn<<<BN * HEADS, 256, ATTN_SMEM_BYTES>>>(dww, dwb);
    wwa_casc<<<BN, 512, SMEM_BYTES>>>(pb, iwtf, out);
}

// round 11
// speedup vs baseline: 1.5105x; 1.0048x over previous
#include <cuda_runtime.h>

#define BATCH 2
#define DIM   256
#define HEADS 8
#define HD    32
#define RES   256
#define FWS   8
#define BN    512            // BATCH * 16 * 16 windows
#define NPIX  64
#define ATTN_SCALE 0.17677669529663689f

// ---------------- device scratch ----------------
__device__ float g_sub[(size_t)4 * BN * DIM * NPIX];          // [s][w][c][n]  134.2 MB
__device__ float g_bias[HEADS * NPIX * NPIX];                 // 128 KB
__device__ float g_attn[(size_t)BN * HEADS * NPIX * NPIX];    // softmaxed attn, 67 MB
__device__ float g_pwT[DIM * DIM];                            // transposed proj weight

typedef unsigned long long u64;

__device__ __forceinline__ u64 pack2(float lo, float hi) {
    u64 r; asm("mov.b64 %0,{%1,%2};" : "=l"(r) : "f"(lo), "f"(hi)); return r;
}
__device__ __forceinline__ void unpack2(u64 v, float& a, float& b) {
    asm("mov.b64 {%0,%1},%2;" : "=f"(a), "=f"(b) : "l"(v));
}
__device__ __forceinline__ void fma2(u64& d, u64 a, u64 b) {
    asm("fma.rn.f32x2 %0,%1,%2,%0;" : "+l"(d) : "l"(a), "l"(b));
}

// ---------------- bias gather ----------------
__global__ void wwa_bias(const float* __restrict__ ab, const int* __restrict__ idxs, int n_off) {
    int idx = blockIdx.x * 256 + threadIdx.x;
    int i = idx >> 12, r = idx & 4095;
    g_bias[idx] = ab[i * n_off + idxs[r]];
}

// ---------------- proj weight transpose: g_pwT[c][o] = pw[o][c] -------------
__global__ void wwa_pwT(const float* __restrict__ pw) {
    __shared__ float tile[32][33];
    int bo = blockIdx.x & 7, bc = blockIdx.x >> 3;
    int lx = threadIdx.x & 31, ly = threadIdx.x >> 5;   // 256 threads: 32x8
    for (int r = ly; r < 32; r += 8)
        tile[r][lx] = pw[(bo * 32 + r) * 256 + bc * 32 + lx];
    __syncthreads();
    for (int r = ly; r < 32; r += 8)
        g_pwT[(bc * 32 + r) * 256 + bo * 32 + lx] = tile[lx][r];
}

// ---------------- wavelet transform ----------------
__global__ void wwa_wt(const float* __restrict__ x, const float* __restrict__ wf) {
    int g = blockIdx.x * 256 + threadIdx.x;
    int pair = g & 31;
    int c = (g >> 5) & 255;
    int w = g >> 13;
    int b = w >> 8, wy = (w >> 4) & 15, wx = w & 15;
    int n0 = pair * 2;
    int p = wy * 8 + (n0 >> 3);
    int q0 = wx * 8 + (n0 & 7);
    const float* xp = x + ((size_t)(b * DIM + c) * RES + 2 * p) * RES + 2 * q0;
    float4 r0 = *(const float4*)xp;
    float4 r1 = *(const float4*)(xp + RES);
    const float4* wf4 = (const float4*)wf;
    float* dst = g_sub + ((size_t)w * DIM + c) * NPIX + n0;
#pragma unroll
    for (int s = 0; s < 4; s++) {
        float4 f = wf4[4 * c + s];
        float o0 = r0.x * f.x + r0.y * f.y + r1.x * f.z + r1.y * f.w;
        float o1 = r0.z * f.x + r0.w * f.y + r1.z * f.z + r1.w * f.w;
        *(float2*)(dst + (size_t)s * BN * DIM * NPIX) = make_float2(o0, o1);
    }
}

// ---------------- attention precompute (unchanged, R9-proven) ----------------
#define A_T   0
#define A_DWW 6272
#define A_DWB 7072
#define A_Q   7104
#define A_K   11456
#define A_TOT 13632
#define ATTN_SMEM_BYTES (A_TOT * 4)

__global__ __launch_bounds__(256)
void wwa_attn(const float* __restrict__ dww, const float* __restrict__ dwb) {
    extern __shared__ float sm[];
    const int t = threadIdx.x;
    const int wh = blockIdx.x;
    const int w = wh >> 3, i = wh & 7;
    const float4* lhp4 = (const float4*)(g_sub + ((size_t)BN + w) * 16384 + i * 2048);
    const float4* hlp4 = (const float4*)(g_sub + ((size_t)2 * BN + w) * 16384 + i * 2048);

    for (int k = t; k < 1568; k += 256)
        ((float4*)sm)[k] = make_float4(0.f, 0.f, 0.f, 0.f);
    __syncthreads();
    for (int k = t; k < 512; k += 256) {
        float4 v = lhp4[k];
        int c = k >> 4, n0 = (k & 15) * 4;
        int off = A_T + c * 196 + ((n0 >> 3) + 2) * 16 + (n0 & 7) + 2;
        *(float2*)&sm[off]     = make_float2(v.x, v.y);
        *(float2*)&sm[off + 2] = make_float2(v.z, v.w);
        float4 u = hlp4[k];
        *(float4*)&sm[A_K + c * 68 + n0] = u;
    }
    for (int k = t; k < 800; k += 256) sm[A_DWW + k] = dww[i * 800 + k];
    if (t < 32) sm[A_DWB + t] = dwb[i * 32 + t];
    __syncthreads();

    {
        const int d = t & 31, py = t >> 5;
        float acc[8];
        float bb = sm[A_DWB + d];
#pragma unroll
        for (int qx = 0; qx < 8; qx++) acc[qx] = bb;
        const float* wp = &sm[A_DWW + d * 25];
        const float* tp = &sm[A_T + d * 196 + py * 16];
#pragma unroll
        for (int ii = 0; ii < 5; ii++) {
            float4 ra = *(const float4*)&tp[ii * 16];
            float4 rb = *(const float4*)&tp[ii * 16 + 4];
            float4 rc = *(const float4*)&tp[ii * 16 + 8];
            float row[12] = {ra.x, ra.y, ra.z, ra.w,
                             rb.x, rb.y, rb.z, rb.w,
                             rc.x, rc.y, rc.z, rc.w};
#pragma unroll
            for (int jj = 0; jj < 5; jj++) {
                float wv = wp[ii * 5 + jj];
#pragma unroll
                for (int qx = 0; qx < 8; qx++)
                    acc[qx] += row[qx + jj] * wv;
            }
        }
#pragma unroll
        for (int qx = 0; qx < 8; qx++) {
            int n = py * 8 + qx;
            *(u64*)&sm[A_Q + n * 68 + 2 * d] = pack2(acc[qx], acc[qx]);
        }
    }
    __syncthreads();

    {
        const int rg = t >> 4, cg = t & 15, m0 = cg * 4;
        u64 acc[4][2] = {};
#pragma unroll 4
        for (int d = 0; d < 32; d += 2) {
            longlong2 ka = *(const longlong2*)&sm[A_K + d * 68 + m0];
            longlong2 kb = *(const longlong2*)&sm[A_K + (d + 1) * 68 + m0];
#pragma unroll
            for (int r = 0; r < 4; r++) {
                longlong2 q2 = *(const longlong2*)&sm[A_Q + (rg * 4 + r) * 68 + 2 * d];
                fma2(acc[r][0], (u64)q2.x, (u64)ka.x);
                fma2(acc[r][1], (u64)q2.x, (u64)ka.y);
                fma2(acc[r][0], (u64)q2.y, (u64)kb.x);
                fma2(acc[r][1], (u64)q2.y, (u64)kb.y);
            }
        }
        float* ap = g_attn + (size_t)wh * 4096;
#pragma unroll
        for (int r = 0; r < 4; r++) {
            int n = rg * 4 + r;
            float v0, v1, v2, v3;
            unpack2(acc[r][0], v0, v1);
            unpack2(acc[r][1], v2, v3);
            const float4 bv = *(const float4*)&g_bias[i * 4096 + n * 64 + m0];
            v0 = v0 * ATTN_SCALE + bv.x; v1 = v1 * ATTN_SCALE + bv.y;
            v2 = v2 * ATTN_SCALE + bv.z; v3 = v3 * ATTN_SCALE + bv.w;
            float mx = fmaxf(fmaxf(v0, v1), fmaxf(v2, v3));
#pragma unroll
            for (int off = 8; off >= 1; off >>= 1)
                mx = fmaxf(mx, __shfl_xor_sync(0xffffffffu, mx, off));
            v0 = __expf(v0 - mx); v1 = __expf(v1 - mx);
            v2 = __expf(v2 - mx); v3 = __expf(v3 - mx);
            float s = v0 + v1 + v2 + v3;
#pragma unroll
            for (int off = 8; off >= 1; off >>= 1)
                s += __shfl_xor_sync(0xffffffffu, s, off);
            float inv = __fdividef(1.f, s);
            *(float4*)&ap[n * 64 + m0] = make_float4(v0 * inv, v1 * inv, v2 * inv, v3 * inv);
        }
    }
}

// ---------------- cascade + projection + inverse WT (v5) ---------------------
// smem float offsets:
//   C_OUT [256][68] = 17408   relu'd cat; later reused to hold proj results P
//   C_ATT [64][64]  =  4096   attn tile
//   C_V0 / C_V1     =  2048 each: V [32][64], XOR-swizzled
#define C_OUT 0
#define C_ATT 17408
#define C_V0  21504
#define C_V1  23552
#define SMEM_FLOATS 25600
#define SMEM_BYTES  (SMEM_FLOATS * 4)

__global__ __launch_bounds__(512, 2)
void wwa_casc(const float* __restrict__ pbias, const float* __restrict__ iwt,
              float* __restrict__ out) {
    extern __shared__ float sm[];
    const int t = threadIdx.x;
    const int w = blockIdx.x;
    const int b = w >> 8, wy = (w >> 4) & 15, wx = w & 15;
    const float* subw0 = g_sub + (size_t)w * 16384;
    const float* subw1 = g_sub + ((size_t)BN + w) * 16384;
    const float* subw2 = g_sub + ((size_t)2 * BN + w) * 16384;
    const float* subw3 = g_sub + ((size_t)3 * BN + w) * 16384;

    // ============ phase 1: cascade AV (swizzled V, double-buffered, no TMP) ====
    const int d = t & 31, n0g = t >> 5;          // lane = d, warp picks n0 group
    const int n0 = n0g * 4;
    const int sw = d & 15;
    const int vslot = d * 64 + 4 * (n0g ^ sw);   // this thread's V float4 slot
    const float4* llp4 = (const float4*)subw0;   // [i*512 + d*16 + n0g]
    const float4* atp4 = (const float4*)(g_attn + (size_t)(w << 3) * 4096);

    // prefetch head 0
    float4 at0 = atp4[t];
    float4 at1 = atp4[t + 512];
    float4 llnext = __ldg(&llp4[d * 16 + n0g]);  // ll for head 0 (V0 init)

#pragma unroll 1
    for (int i = 0; i < 8; i++) {
        // stage attn tile (prev AV readers finished at previous end-barrier)
        ((float4*)&sm[C_ATT])[t]       = at0;
        ((float4*)&sm[C_ATT])[t + 512] = at1;
        if (i == 0)
            *(float4*)&sm[C_V0 + vslot] = llnext;  // V0 = ll0
        __syncthreads();
        // prefetch next head while computing this one
        if (i < 7) {
            at0 = atp4[(i + 1) * 1024 + t];
            at1 = atp4[(i + 1) * 1024 + t + 512];
            llnext = __ldg(&llp4[(i + 1) * 512 + d * 16 + n0g]);
        }

        // out[d][n] = sum_m v[d][m] * attn[n][m]
        const int vb_off = (i & 1) ? C_V1 : C_V0;
        u64 acc[4] = {};
#pragma unroll
        for (int g = 0; g < 8; g++) {            // m = 8g .. 8g+7
            longlong2 va = *(const longlong2*)&sm[vb_off + d * 64 + 4 * ((2 * g) ^ sw)];
            longlong2 vb = *(const longlong2*)&sm[vb_off + d * 64 + 4 * ((2 * g + 1) ^ sw)];
#pragma unroll
            for (int j = 0; j < 4; j++) {
                const longlong2* ar = (const longlong2*)&sm[C_ATT + (n0 + j) * 64 + 8 * g];
                longlong2 a0 = ar[0], a1 = ar[1];
                fma2(acc[j], (u64)va.x, (u64)a0.x);
                fma2(acc[j], (u64)va.y, (u64)a0.y);
                fma2(acc[j], (u64)vb.x, (u64)a1.x);
                fma2(acc[j], (u64)vb.y, (u64)a1.y);
            }
        }
        float v0l, v0h, v1l, v1h, v2l, v2h, v3l, v3h;
        unpack2(acc[0], v0l, v0h); unpack2(acc[1], v1l, v1h);
        unpack2(acc[2], v2l, v2h); unpack2(acc[3], v3l, v3h);
        float4 raw = make_float4(v0l + v0h, v1l + v1h, v2l + v2h, v3l + v3h);
        *(float4*)&sm[C_OUT + (i * 32 + d) * 68 + n0] =
            make_float4(fmaxf(raw.x, 0.f), fmaxf(raw.y, 0.f),
                        fmaxf(raw.z, 0.f), fmaxf(raw.w, 0.f));
        if (i < 7) {
            // V_{i+1} = raw + ll_{i+1}, into alternate buffer
            float4 vn = make_float4(raw.x + llnext.x, raw.y + llnext.y,
                                    raw.z + llnext.z, raw.w + llnext.w);
            int alt = (i & 1) ? C_V0 : C_V1;
            *(float4*)&sm[alt + vslot] = vn;
        }
        __syncthreads();
    }

    // ============ phase 2: projection (weights via coalesced __ldg) ============
    const int o = t & 255, half = t >> 8;
    u64 acc[16];
    {
        float pbv = pbias[o];
        u64 pi = pack2(pbv, pbv);
#pragma unroll
        for (int u = 0; u < 16; u++) acc[u] = pi;
    }
#pragma unroll 4
    for (int c = 0; c < 256; c++) {
        float wv = __ldg(&g_pwT[c * 256 + o]);
        u64 w2 = pack2(wv, wv);
        const longlong2* row = (const longlong2*)&sm[C_OUT + c * 68 + half * 32];
#pragma unroll
        for (int u = 0; u < 8; u++) {
            longlong2 p = row[u];
            fma2(acc[2 * u],     w2, (u64)p.x);
            fma2(acc[2 * u + 1], w2, (u64)p.y);
        }
    }
    __syncthreads();   // all cat reads done; C_OUT becomes P
#pragma unroll
    for (int u = 0; u < 8; u++) {
        longlong2 p;
        p.x = (long long)acc[2 * u];
        p.y = (long long)acc[2 * u + 1];
        *(longlong2*)&sm[C_OUT + o * 68 + half * 32 + u * 4] = p;
    }
    __syncthreads();   // P visible to all

    // ============ phase 3: inverse WT epilogue (barrier-free, direct LDG) ======
    const int oo = t >> 4, m = t & 15;        // oo 0..31, output row m 0..15
    const int py = m >> 1, ry = m & 1;        // source pixel row, sub-row
    float* obase = out + (size_t)(b * DIM) * RES * RES
                 + (size_t)(wy * 16 + m) * RES + wx * 16;

#pragma unroll 1
    for (int obk = 0; obk < 8; obk++) {
        const int og = obk * 32 + oo;
        const float* iwp = iwt + og * 16 + 2 * ry;
        float c00 = __ldg(iwp + 0),  c01 = __ldg(iwp + 1);
        float c10 = __ldg(iwp + 4),  c11 = __ldg(iwp + 5);
        float c20 = __ldg(iwp + 8),  c21 = __ldg(iwp + 9);
        float c30 = __ldg(iwp + 12), c31 = __ldg(iwp + 13);
        const int nb = og * 64 + 8 * py;
        float4 lhA = __ldg((const float4*)(subw1 + nb));
        float4 lhB = __ldg((const float4*)(subw1 + nb + 4));
        float4 hlA = __ldg((const float4*)(subw2 + nb));
        float4 hlB = __ldg((const float4*)(subw2 + nb + 4));
        float4 hhA = __ldg((const float4*)(subw3 + nb));
        float4 hhB = __ldg((const float4*)(subw3 + nb + 4));
        float4 pA = *(const float4*)&sm[C_OUT + og * 68 + 8 * py];
        float4 pB = *(const float4*)&sm[C_OUT + og * 68 + 8 * py + 4];
        float* orow = obase + (size_t)og * (RES * RES);

        float4 r0, r1, r2, r3;
        r0.x = pA.x * c00 + lhA.x * c10 + hlA.x * c20 + hhA.x * c30;
        r0.y = pA.x * c01 + lhA.x * c11 + hlA.x * c21 + hhA.x * c31;
        r0.z = pA.y * c00 + lhA.y * c10 + hlA.y * c20 + hhA.y * c30;
        r0.w = pA.y * c01 + lhA.y * c11 + hlA.y * c21 + hhA.y * c31;
        r1.x = pA.z * c00 + lhA.z * c10 + hlA.z * c20 + hhA.z * c30;
        r1.y = pA.z * c01 + lhA.z * c11 + hlA.z * c21 + hhA.z * c31;
        r1.z = pA.w * c00 + lhA.w * c10 + hlA.w * c20 + hhA.w * c30;
        r1.w = pA.w * c01 + lhA.w * c11 + hlA.w * c21 + hhA.w * c31;
        r2.x = pB.x * c00 + lhB.x * c10 + hlB.x * c20 + hhB.x * c30;
        r2.y = pB.x * c01 + lhB.x * c11 + hlB.x * c21 + hhB.x * c31;
        r2.z = pB.y * c00 + lhB.y * c10 + hlB.y * c20 + hhB.y * c30;
        r2.w = pB.y * c01 + lhB.y * c11 + hlB.y * c21 + hhB.y * c31;
        r3.x = pB.z * c00 + lhB.z * c10 + hlB.z * c20 + hhB.z * c30;
        r3.y = pB.z * c01 + lhB.z * c11 + hlB.z * c21 + hhB.z * c31;
        r3.z = pB.w * c00 + lhB.w * c10 + hlB.w * c20 + hhB.w * c30;
        r3.w = pB.w * c01 + lhB.w * c11 + hlB.w * c21 + hhB.w * c31;
        *(float4*)&orow[0]  = r0;
        *(float4*)&orow[4]  = r1;
        *(float4*)&orow[8]  = r2;
        *(float4*)&orow[12] = r3;
    }
}

extern "C" void kernel_launch(void* const* d_in, const int* in_sizes, int n_in,
                              void* d_out, int out_size) {
    const float* x    = (const float*)d_in[0];
    const float* wtf  = (const float*)d_in[1];
    const float* iwtf = (const float*)d_in[2];
    const float* dww  = (const float*)d_in[3];
    const float* dwb  = (const float*)d_in[4];
    const float* pw   = (const float*)d_in[5];
    const float* pb   = (const float*)d_in[6];
    const float* ab   = (const float*)d_in[7];
    const int*   idxs = (const int*)d_in[8];
    int n_off = in_sizes[7] / HEADS;
    float* out = (float*)d_out;

    cudaFuncSetAttribute(wwa_attn, cudaFuncAttributeMaxDynamicSharedMemorySize, ATTN_SMEM_BYTES);
    cudaFuncSetAttribute(wwa_casc, cudaFuncAttributeMaxDynamicSharedMemorySize, SMEM_BYTES);

    wwa_bias<<<128, 256>>>(ab, idxs, n_off);
    wwa_pwT<<<64, 256>>>(pw);
    wwa_wt<<<16384, 256>>>(x, wtf);
    wwa_attn<<<BN * HEADS, 256, ATTN_SMEM_BYTES>>>(dww, dwb);
    wwa_casc<<<BN, 512, SMEM_BYTES>>>(pb, iwtf, out);
}

// round 12
// speedup vs baseline: 1.5230x; 1.0083x over previous
#include <cuda_runtime.h>

#define BATCH 2
#define DIM   256
#define HEADS 8
#define HD    32
#define RES   256
#define FWS   8
#define BN    512            // BATCH * 16 * 16 windows
#define NPIX  64
#define ATTN_SCALE 0.17677669529663689f

// ---------------- device scratch ----------------
__device__ float g_sub[(size_t)4 * BN * DIM * NPIX];          // [s][w][c][n]  134.2 MB
__device__ float g_bias[HEADS * NPIX * NPIX];                 // 128 KB
__device__ float g_attn[(size_t)BN * HEADS * NPIX * NPIX];    // softmaxed attn, 67 MB
__device__ float g_pwI[DIM * DIM];                            // c-interleaved proj weight
                                                              // g_pwI[(c>>2)*1024 + o*4 + (c&3)] = pw[o][c]

typedef unsigned long long u64;

__device__ __forceinline__ u64 pack2(float lo, float hi) {
    u64 r; asm("mov.b64 %0,{%1,%2};" : "=l"(r) : "f"(lo), "f"(hi)); return r;
}
__device__ __forceinline__ void unpack2(u64 v, float& a, float& b) {
    asm("mov.b64 {%0,%1},%2;" : "=f"(a), "=f"(b) : "l"(v));
}
__device__ __forceinline__ void fma2(u64& d, u64 a, u64 b) {
    asm("fma.rn.f32x2 %0,%1,%2,%0;" : "+l"(d) : "l"(a), "l"(b));
}

// ---------------- prep: bias gather + proj weight interleave -----------------
__global__ void wwa_prep(const float* __restrict__ ab, const int* __restrict__ idxs,
                         int n_off, const float* __restrict__ pw) {
    int blk = blockIdx.x, t = threadIdx.x;
    if (blk < 128) {
        int idx = blk * 256 + t;                 // 0..32767
        int i = idx >> 12, r = idx & 4095;
        g_bias[idx] = ab[i * n_off + idxs[r]];
    } else {
        int base = (blk - 128) * 512;
#pragma unroll
        for (int rep = 0; rep < 2; rep++) {
            int u = base + t + rep * 256;        // 0..65535, coalesced read
            int o = u >> 8, c = u & 255;
            g_pwI[(c >> 2) * 1024 + o * 4 + (c & 3)] = pw[u];
        }
    }
}

// ---------------- wavelet transform ----------------
__global__ void wwa_wt(const float* __restrict__ x, const float* __restrict__ wf) {
    int g = blockIdx.x * 256 + threadIdx.x;
    int pair = g & 31;
    int c = (g >> 5) & 255;
    int w = g >> 13;
    int b = w >> 8, wy = (w >> 4) & 15, wx = w & 15;
    int n0 = pair * 2;
    int p = wy * 8 + (n0 >> 3);
    int q0 = wx * 8 + (n0 & 7);
    const float* xp = x + ((size_t)(b * DIM + c) * RES + 2 * p) * RES + 2 * q0;
    float4 r0 = *(const float4*)xp;
    float4 r1 = *(const float4*)(xp + RES);
    const float4* wf4 = (const float4*)wf;
    float* dst = g_sub + ((size_t)w * DIM + c) * NPIX + n0;
#pragma unroll
    for (int s = 0; s < 4; s++) {
        float4 f = wf4[4 * c + s];
        float o0 = r0.x * f.x + r0.y * f.y + r1.x * f.z + r1.y * f.w;
        float o1 = r0.z * f.x + r0.w * f.y + r1.z * f.z + r1.w * f.w;
        *(float2*)(dst + (size_t)s * BN * DIM * NPIX) = make_float2(o0, o1);
    }
}

// ---------------- attention precompute (unchanged, R9-proven) ----------------
#define A_T   0
#define A_DWW 6272
#define A_DWB 7072
#define A_Q   7104
#define A_K   11456
#define A_TOT 13632
#define ATTN_SMEM_BYTES (A_TOT * 4)

__global__ __launch_bounds__(256)
void wwa_attn(const float* __restrict__ dww, const float* __restrict__ dwb) {
    extern __shared__ float sm[];
    const int t = threadIdx.x;
    const int wh = blockIdx.x;
    const int w = wh >> 3, i = wh & 7;
    const float4* lhp4 = (const float4*)(g_sub + ((size_t)BN + w) * 16384 + i * 2048);
    const float4* hlp4 = (const float4*)(g_sub + ((size_t)2 * BN + w) * 16384 + i * 2048);

    for (int k = t; k < 1568; k += 256)
        ((float4*)sm)[k] = make_float4(0.f, 0.f, 0.f, 0.f);
    __syncthreads();
    for (int k = t; k < 512; k += 256) {
        float4 v = lhp4[k];
        int c = k >> 4, n0 = (k & 15) * 4;
        int off = A_T + c * 196 + ((n0 >> 3) + 2) * 16 + (n0 & 7) + 2;
        *(float2*)&sm[off]     = make_float2(v.x, v.y);
        *(float2*)&sm[off + 2] = make_float2(v.z, v.w);
        float4 u = hlp4[k];
        *(float4*)&sm[A_K + c * 68 + n0] = u;
    }
    for (int k = t; k < 800; k += 256) sm[A_DWW + k] = dww[i * 800 + k];
    if (t < 32) sm[A_DWB + t] = dwb[i * 32 + t];
    __syncthreads();

    {
        const int d = t & 31, py = t >> 5;
        float acc[8];
        float bb = sm[A_DWB + d];
#pragma unroll
        for (int qx = 0; qx < 8; qx++) acc[qx] = bb;
        const float* wp = &sm[A_DWW + d * 25];
        const float* tp = &sm[A_T + d * 196 + py * 16];
#pragma unroll
        for (int ii = 0; ii < 5; ii++) {
            float4 ra = *(const float4*)&tp[ii * 16];
            float4 rb = *(const float4*)&tp[ii * 16 + 4];
            float4 rc = *(const float4*)&tp[ii * 16 + 8];
            float row[12] = {ra.x, ra.y, ra.z, ra.w,
                             rb.x, rb.y, rb.z, rb.w,
                             rc.x, rc.y, rc.z, rc.w};
#pragma unroll
            for (int jj = 0; jj < 5; jj++) {
                float wv = wp[ii * 5 + jj];
#pragma unroll
                for (int qx = 0; qx < 8; qx++)
                    acc[qx] += row[qx + jj] * wv;
            }
        }
#pragma unroll
        for (int qx = 0; qx < 8; qx++) {
            int n = py * 8 + qx;
            *(u64*)&sm[A_Q + n * 68 + 2 * d] = pack2(acc[qx], acc[qx]);
        }
    }
    __syncthreads();

    {
        const int rg = t >> 4, cg = t & 15, m0 = cg * 4;
        u64 acc[4][2] = {};
#pragma unroll 4
        for (int d = 0; d < 32; d += 2) {
            longlong2 ka = *(const longlong2*)&sm[A_K + d * 68 + m0];
            longlong2 kb = *(const longlong2*)&sm[A_K + (d + 1) * 68 + m0];
#pragma unroll
            for (int r = 0; r < 4; r++) {
                longlong2 q2 = *(const longlong2*)&sm[A_Q + (rg * 4 + r) * 68 + 2 * d];
                fma2(acc[r][0], (u64)q2.x, (u64)ka.x);
                fma2(acc[r][1], (u64)q2.x, (u64)ka.y);
                fma2(acc[r][0], (u64)q2.y, (u64)kb.x);
                fma2(acc[r][1], (u64)q2.y, (u64)kb.y);
            }
        }
        float* ap = g_attn + (size_t)wh * 4096;
#pragma unroll
        for (int r = 0; r < 4; r++) {
            int n = rg * 4 + r;
            float v0, v1, v2, v3;
            unpack2(acc[r][0], v0, v1);
            unpack2(acc[r][1], v2, v3);
            const float4 bv = *(const float4*)&g_bias[i * 4096 + n * 64 + m0];
            v0 = v0 * ATTN_SCALE + bv.x; v1 = v1 * ATTN_SCALE + bv.y;
            v2 = v2 * ATTN_SCALE + bv.z; v3 = v3 * ATTN_SCALE + bv.w;
            float mx = fmaxf(fmaxf(v0, v1), fmaxf(v2, v3));
#pragma unroll
            for (int off = 8; off >= 1; off >>= 1)
                mx = fmaxf(mx, __shfl_xor_sync(0xffffffffu, mx, off));
            v0 = __expf(v0 - mx); v1 = __expf(v1 - mx);
            v2 = __expf(v2 - mx); v3 = __expf(v3 - mx);
            float s = v0 + v1 + v2 + v3;
#pragma unroll
            for (int off = 8; off >= 1; off >>= 1)
                s += __shfl_xor_sync(0xffffffffu, s, off);
            float inv = __fdividef(1.f, s);
            *(float4*)&ap[n * 64 + m0] = make_float4(v0 * inv, v1 * inv, v2 * inv, v3 * inv);
        }
    }
}

// ---------------- cascade + projection + inverse WT (v6) ---------------------
#define C_OUT 0
#define C_ATT 17408
#define C_V0  21504
#define C_V1  23552
#define SMEM_FLOATS 25600
#define SMEM_BYTES  (SMEM_FLOATS * 4)

__global__ __launch_bounds__(512, 2)
void wwa_casc(const float* __restrict__ pbias, const float* __restrict__ iwt,
              float* __restrict__ out) {
    extern __shared__ float sm[];
    const int t = threadIdx.x;
    const int w = blockIdx.x;
    const int b = w >> 8, wy = (w >> 4) & 15, wx = w & 15;
    const float* subw0 = g_sub + (size_t)w * 16384;
    const float* subw1 = g_sub + ((size_t)BN + w) * 16384;
    const float* subw2 = g_sub + ((size_t)2 * BN + w) * 16384;
    const float* subw3 = g_sub + ((size_t)3 * BN + w) * 16384;

    // ============ phase 1: cascade AV (swizzled V, double-buffered) ============
    const int d = t & 31, n0g = t >> 5;
    const int n0 = n0g * 4;
    const int sw = d & 15;
    const int vslot = d * 64 + 4 * (n0g ^ sw);
    const float4* llp4 = (const float4*)subw0;
    const float4* atp4 = (const float4*)(g_attn + (size_t)(w << 3) * 4096);

    float4 at0 = atp4[t];
    float4 at1 = atp4[t + 512];
    float4 llnext = __ldg(&llp4[d * 16 + n0g]);

#pragma unroll 1
    for (int i = 0; i < 8; i++) {
        ((float4*)&sm[C_ATT])[t]       = at0;
        ((float4*)&sm[C_ATT])[t + 512] = at1;
        if (i == 0)
            *(float4*)&sm[C_V0 + vslot] = llnext;
        __syncthreads();
        if (i < 7) {
            at0 = atp4[(i + 1) * 1024 + t];
            at1 = atp4[(i + 1) * 1024 + t + 512];
            llnext = __ldg(&llp4[(i + 1) * 512 + d * 16 + n0g]);
        }

        const int vb_off = (i & 1) ? C_V1 : C_V0;
        u64 acc[4] = {};
#pragma unroll
        for (int g = 0; g < 8; g++) {
            longlong2 va = *(const longlong2*)&sm[vb_off + d * 64 + 4 * ((2 * g) ^ sw)];
            longlong2 vb = *(const longlong2*)&sm[vb_off + d * 64 + 4 * ((2 * g + 1) ^ sw)];
#pragma unroll
            for (int j = 0; j < 4; j++) {
                const longlong2* ar = (const longlong2*)&sm[C_ATT + (n0 + j) * 64 + 8 * g];
                longlong2 a0 = ar[0], a1 = ar[1];
                fma2(acc[j], (u64)va.x, (u64)a0.x);
                fma2(acc[j], (u64)va.y, (u64)a0.y);
                fma2(acc[j], (u64)vb.x, (u64)a1.x);
                fma2(acc[j], (u64)vb.y, (u64)a1.y);
            }
        }
        float v0l, v0h, v1l, v1h, v2l, v2h, v3l, v3h;
        unpack2(acc[0], v0l, v0h); unpack2(acc[1], v1l, v1h);
        unpack2(acc[2], v2l, v2h); unpack2(acc[3], v3l, v3h);
        float4 raw = make_float4(v0l + v0h, v1l + v1h, v2l + v2h, v3l + v3h);
        *(float4*)&sm[C_OUT + (i * 32 + d) * 68 + n0] =
            make_float4(fmaxf(raw.x, 0.f), fmaxf(raw.y, 0.f),
                        fmaxf(raw.z, 0.f), fmaxf(raw.w, 0.f));
        if (i < 7) {
            float4 vn = make_float4(raw.x + llnext.x, raw.y + llnext.y,
                                    raw.z + llnext.z, raw.w + llnext.w);
            int alt = (i & 1) ? C_V0 : C_V1;
            *(float4*)&sm[alt + vslot] = vn;
        }
        __syncthreads();
    }

    // ============ phase 2: projection (interleaved float4 weight loads) ========
    const int o = t & 255, half = t >> 8;
    u64 acc[16];
    {
        float pbv = pbias[o];
        u64 pi = pack2(pbv, pbv);
#pragma unroll
        for (int u = 0; u < 16; u++) acc[u] = pi;
    }
    const float4* wip = (const float4*)(g_pwI + o * 4);     // + cg*256 float4s
#pragma unroll 2
    for (int cg = 0; cg < 64; cg++) {
        const float4 wv4 = __ldg(wip + cg * 256);           // w[4cg..4cg+3][o]
        const int cb = cg * 4;
#pragma unroll
        for (int s = 0; s < 4; s++) {
            float wv = (s == 0) ? wv4.x : (s == 1) ? wv4.y : (s == 2) ? wv4.z : wv4.w;
            u64 w2 = pack2(wv, wv);
            const longlong2* row = (const longlong2*)&sm[C_OUT + (cb + s) * 68 + half * 32];
            longlong2 p0 = row[0], p1 = row[1], p2 = row[2], p3 = row[3];
            fma2(acc[0], w2, (u64)p0.x);  fma2(acc[1], w2, (u64)p0.y);
            fma2(acc[2], w2, (u64)p1.x);  fma2(acc[3], w2, (u64)p1.y);
            fma2(acc[4], w2, (u64)p2.x);  fma2(acc[5], w2, (u64)p2.y);
            fma2(acc[6], w2, (u64)p3.x);  fma2(acc[7], w2, (u64)p3.y);
            longlong2 p4 = row[4], p5 = row[5], p6 = row[6], p7 = row[7];
            fma2(acc[8],  w2, (u64)p4.x); fma2(acc[9],  w2, (u64)p4.y);
            fma2(acc[10], w2, (u64)p5.x); fma2(acc[11], w2, (u64)p5.y);
            fma2(acc[12], w2, (u64)p6.x); fma2(acc[13], w2, (u64)p6.y);
            fma2(acc[14], w2, (u64)p7.x); fma2(acc[15], w2, (u64)p7.y);
        }
    }
    __syncthreads();   // all cat reads done; C_OUT becomes P
#pragma unroll
    for (int u = 0; u < 8; u++) {
        longlong2 p;
        p.x = (long long)acc[2 * u];
        p.y = (long long)acc[2 * u + 1];
        *(longlong2*)&sm[C_OUT + o * 68 + half * 32 + u * 4] = p;
    }
    __syncthreads();   // P visible to all

    // ============ phase 3: inverse WT epilogue (barrier-free, direct LDG) ======
    const int oo = t >> 4, m = t & 15;
    const int py = m >> 1, ry = m & 1;
    float* obase = out + (size_t)(b * DIM) * RES * RES
                 + (size_t)(wy * 16 + m) * RES + wx * 16;

#pragma unroll 1
    for (int obk = 0; obk < 8; obk++) {
        const int og = obk * 32 + oo;
        const float* iwp = iwt + og * 16 + 2 * ry;
        float c00 = __ldg(iwp + 0),  c01 = __ldg(iwp + 1);
        float c10 = __ldg(iwp + 4),  c11 = __ldg(iwp + 5);
        float c20 = __ldg(iwp + 8),  c21 = __ldg(iwp + 9);
        float c30 = __ldg(iwp + 12), c31 = __ldg(iwp + 13);
        const int nb = og * 64 + 8 * py;
        float4 lhA = __ldg((const float4*)(subw1 + nb));
        float4 lhB = __ldg((const float4*)(subw1 + nb + 4));
        float4 hlA = __ldg((const float4*)(subw2 + nb));
        float4 hlB = __ldg((const float4*)(subw2 + nb + 4));
        float4 hhA = __ldg((const float4*)(subw3 + nb));
        float4 hhB = __ldg((const float4*)(subw3 + nb + 4));
        float4 pA = *(const float4*)&sm[C_OUT + og * 68 + 8 * py];
        float4 pB = *(const float4*)&sm[C_OUT + og * 68 + 8 * py + 4];
        float* orow = obase + (size_t)og * (RES * RES);

        float4 r0, r1, r2, r3;
        r0.x = pA.x * c00 + lhA.x * c10 + hlA.x * c20 + hhA.x * c30;
        r0.y = pA.x * c01 + lhA.x * c11 + hlA.x * c21 + hhA.x * c31;
        r0.z = pA.y * c00 + lhA.y * c10 + hlA.y * c20 + hhA.y * c30;
        r0.w = pA.y * c01 + lhA.y * c11 + hlA.y * c21 + hhA.y * c31;
        r1.x = pA.z * c00 + lhA.z * c10 + hlA.z * c20 + hhA.z * c30;
        r1.y = pA.z * c01 + lhA.z * c11 + hlA.z * c21 + hhA.z * c31;
        r1.z = pA.w * c00 + lhA.w * c10 + hlA.w * c20 + hhA.w * c30;
        r1.w = pA.w * c01 + lhA.w * c11 + hlA.w * c21 + hhA.w * c31;
        r2.x = pB.x * c00 + lhB.x * c10 + hlB.x * c20 + hhB.x * c30;
        r2.y = pB.x * c01 + lhB.x * c11 + hlB.x * c21 + hhB.x * c31;
        r2.z = pB.y * c00 + lhB.y * c10 + hlB.y * c20 + hhB.y * c30;
        r2.w = pB.y * c01 + lhB.y * c11 + hlB.y * c21 + hhB.y * c31;
        r3.x = pB.z * c00 + lhB.z * c10 + hlB.z * c20 + hhB.z * c30;
        r3.y = pB.z * c01 + lhB.z * c11 + hlB.z * c21 + hhB.z * c31;
        r3.z = pB.w * c00 + lhB.w * c10 + hlB.w * c20 + hhB.w * c30;
        r3.w = pB.w * c01 + lhB.w * c11 + hlB.w * c21 + hhB.w * c31;
        *(float4*)&orow[0]  = r0;
        *(float4*)&orow[4]  = r1;
        *(float4*)&orow[8]  = r2;
        *(float4*)&orow[12] = r3;
    }
}

extern "C" void kernel_launch(void* const* d_in, const int* in_sizes, int n_in,
                              void* d_out, int out_size) {
    const float* x    = (const float*)d_in[0];
    const float* wtf  = (const float*)d_in[1];
    const float* iwtf = (const float*)d_in[2];
    const float* dww  = (const float*)d_in[3];
    const float* dwb  = (const float*)d_in[4];
    const float* pw   = (const float*)d_in[5];
    const float* pb   = (const float*)d_in[6];
    const float* ab   = (const float*)d_in[7];
    const int*   idxs = (const int*)d_in[8];
    int n_off = in_sizes[7] / HEADS;
    float* out = (float*)d_out;

    cudaFuncSetAttribute(wwa_attn, cudaFuncAttributeMaxDynamicSharedMemorySize, ATTN_SMEM_BYTES);
    cudaFuncSetAttribute(wwa_casc, cudaFuncAttributeMaxDynamicSharedMemorySize, SMEM_BYTES);

    wwa_prep<<<256, 256>>>(ab, idxs, n_off, pw);
    wwa_wt<<<16384, 256>>>(x, wtf);
    wwa_attn<<<BN * HEADS, 256, ATTN_SMEM_BYTES>>>(dww, dwb);
    wwa_casc<<<BN, 512, SMEM_BYTES>>>(pb, iwtf, out);
}

// round 13
// speedup vs baseline: 1.6890x; 1.1090x over previous
#include <cuda_runtime.h>

#define BATCH 2
#define DIM   256
#define HEADS 8
#define HD    32
#define RES   256
#define FWS   8
#define BN    512            // BATCH * 16 * 16 windows
#define NPIX  64
#define ATTN_SCALE 0.17677669529663689f

// ---------------- device scratch ----------------
__device__ float g_sub[(size_t)4 * BN * DIM * NPIX];          // [s][w][c][n]  134.2 MB
__device__ float g_bias[HEADS * NPIX * NPIX];                 // 128 KB
__device__ float g_attn[(size_t)BN * HEADS * NPIX * NPIX];    // softmaxed attn, 67 MB
__device__ float g_pwQ[DIM * DIM];                            // quad-interleaved proj weight
                                                              // g_pwQ[(c*64 + (o&63))*4 + (o>>6)] = pw[o][c]

typedef unsigned long long u64;

__device__ __forceinline__ u64 pack2(float lo, float hi) {
    u64 r; asm("mov.b64 %0,{%1,%2};" : "=l"(r) : "f"(lo), "f"(hi)); return r;
}
__device__ __forceinline__ void unpack2(u64 v, float& a, float& b) {
    asm("mov.b64 {%0,%1},%2;" : "=f"(a), "=f"(b) : "l"(v));
}
__device__ __forceinline__ void fma2(u64& d, u64 a, u64 b) {
    asm("fma.rn.f32x2 %0,%1,%2,%0;" : "+l"(d) : "l"(a), "l"(b));
}

// ---------------- prep: bias gather + proj weight quad-interleave ------------
__global__ void wwa_prep(const float* __restrict__ ab, const int* __restrict__ idxs,
                         int n_off, const float* __restrict__ pw) {
    int blk = blockIdx.x, t = threadIdx.x;
    if (blk < 128) {
        int idx = blk * 256 + t;                 // 0..32767
        int i = idx >> 12, r = idx & 4095;
        g_bias[idx] = ab[i * n_off + idxs[r]];
    } else {
        int base = (blk - 128) * 512;
#pragma unroll
        for (int rep = 0; rep < 2; rep++) {
            int u = base + t + rep * 256;        // 0..65535, coalesced read
            int o = u >> 8, c = u & 255;
            g_pwQ[(c * 64 + (o & 63)) * 4 + (o >> 6)] = pw[u];
        }
    }
}

// ---------------- wavelet transform ----------------
__global__ void wwa_wt(const float* __restrict__ x, const float* __restrict__ wf) {
    int g = blockIdx.x * 256 + threadIdx.x;
    int pair = g & 31;
    int c = (g >> 5) & 255;
    int w = g >> 13;
    int b = w >> 8, wy = (w >> 4) & 15, wx = w & 15;
    int n0 = pair * 2;
    int p = wy * 8 + (n0 >> 3);
    int q0 = wx * 8 + (n0 & 7);
    const float* xp = x + ((size_t)(b * DIM + c) * RES + 2 * p) * RES + 2 * q0;
    float4 r0 = *(const float4*)xp;
    float4 r1 = *(const float4*)(xp + RES);
    const float4* wf4 = (const float4*)wf;
    float* dst = g_sub + ((size_t)w * DIM + c) * NPIX + n0;
#pragma unroll
    for (int s = 0; s < 4; s++) {
        float4 f = wf4[4 * c + s];
        float o0 = r0.x * f.x + r0.y * f.y + r1.x * f.z + r1.y * f.w;
        float o1 = r0.z * f.x + r0.w * f.y + r1.z * f.z + r1.w * f.w;
        *(float2*)(dst + (size_t)s * BN * DIM * NPIX) = make_float2(o0, o1);
    }
}

// ---------------- attention precompute (unchanged, R9-proven) ----------------
#define A_T   0
#define A_DWW 6272
#define A_DWB 7072
#define A_Q   7104
#define A_K   11456
#define A_TOT 13632
#define ATTN_SMEM_BYTES (A_TOT * 4)

__global__ __launch_bounds__(256)
void wwa_attn(const float* __restrict__ dww, const float* __restrict__ dwb) {
    extern __shared__ float sm[];
    const int t = threadIdx.x;
    const int wh = blockIdx.x;
    const int w = wh >> 3, i = wh & 7;
    const float4* lhp4 = (const float4*)(g_sub + ((size_t)BN + w) * 16384 + i * 2048);
    const float4* hlp4 = (const float4*)(g_sub + ((size_t)2 * BN + w) * 16384 + i * 2048);

    for (int k = t; k < 1568; k += 256)
        ((float4*)sm)[k] = make_float4(0.f, 0.f, 0.f, 0.f);
    __syncthreads();
    for (int k = t; k < 512; k += 256) {
        float4 v = lhp4[k];
        int c = k >> 4, n0 = (k & 15) * 4;
        int off = A_T + c * 196 + ((n0 >> 3) + 2) * 16 + (n0 & 7) + 2;
        *(float2*)&sm[off]     = make_float2(v.x, v.y);
        *(float2*)&sm[off + 2] = make_float2(v.z, v.w);
        float4 u = hlp4[k];
        *(float4*)&sm[A_K + c * 68 + n0] = u;
    }
    for (int k = t; k < 800; k += 256) sm[A_DWW + k] = dww[i * 800 + k];
    if (t < 32) sm[A_DWB + t] = dwb[i * 32 + t];
    __syncthreads();

    {
        const int d = t & 31, py = t >> 5;
        float acc[8];
        float bb = sm[A_DWB + d];
#pragma unroll
        for (int qx = 0; qx < 8; qx++) acc[qx] = bb;
        const float* wp = &sm[A_DWW + d * 25];
        const float* tp = &sm[A_T + d * 196 + py * 16];
#pragma unroll
        for (int ii = 0; ii < 5; ii++) {
            float4 ra = *(const float4*)&tp[ii * 16];
            float4 rb = *(const float4*)&tp[ii * 16 + 4];
            float4 rc = *(const float4*)&tp[ii * 16 + 8];
            float row[12] = {ra.x, ra.y, ra.z, ra.w,
                             rb.x, rb.y, rb.z, rb.w,
                             rc.x, rc.y, rc.z, rc.w};
#pragma unroll
            for (int jj = 0; jj < 5; jj++) {
                float wv = wp[ii * 5 + jj];
#pragma unroll
                for (int qx = 0; qx < 8; qx++)
                    acc[qx] += row[qx + jj] * wv;
            }
        }
#pragma unroll
        for (int qx = 0; qx < 8; qx++) {
            int n = py * 8 + qx;
            *(u64*)&sm[A_Q + n * 68 + 2 * d] = pack2(acc[qx], acc[qx]);
        }
    }
    __syncthreads();

    {
        const int rg = t >> 4, cg = t & 15, m0 = cg * 4;
        u64 acc[4][2] = {};
#pragma unroll 4
        for (int d = 0; d < 32; d += 2) {
            longlong2 ka = *(const longlong2*)&sm[A_K + d * 68 + m0];
            longlong2 kb = *(const longlong2*)&sm[A_K + (d + 1) * 68 + m0];
#pragma unroll
            for (int r = 0; r < 4; r++) {
                longlong2 q2 = *(const longlong2*)&sm[A_Q + (rg * 4 + r) * 68 + 2 * d];
                fma2(acc[r][0], (u64)q2.x, (u64)ka.x);
                fma2(acc[r][1], (u64)q2.x, (u64)ka.y);
                fma2(acc[r][0], (u64)q2.y, (u64)kb.x);
                fma2(acc[r][1], (u64)q2.y, (u64)kb.y);
            }
        }
        float* ap = g_attn + (size_t)wh * 4096;
#pragma unroll
        for (int r = 0; r < 4; r++) {
            int n = rg * 4 + r;
            float v0, v1, v2, v3;
            unpack2(acc[r][0], v0, v1);
            unpack2(acc[r][1], v2, v3);
            const float4 bv = *(const float4*)&g_bias[i * 4096 + n * 64 + m0];
            v0 = v0 * ATTN_SCALE + bv.x; v1 = v1 * ATTN_SCALE + bv.y;
            v2 = v2 * ATTN_SCALE + bv.z; v3 = v3 * ATTN_SCALE + bv.w;
            float mx = fmaxf(fmaxf(v0, v1), fmaxf(v2, v3));
#pragma unroll
            for (int off = 8; off >= 1; off >>= 1)
                mx = fmaxf(mx, __shfl_xor_sync(0xffffffffu, mx, off));
            v0 = __expf(v0 - mx); v1 = __expf(v1 - mx);
            v2 = __expf(v2 - mx); v3 = __expf(v3 - mx);
            float s = v0 + v1 + v2 + v3;
#pragma unroll
            for (int off = 8; off >= 1; off >>= 1)
                s += __shfl_xor_sync(0xffffffffu, s, off);
            float inv = __fdividef(1.f, s);
            *(float4*)&ap[n * 64 + m0] = make_float4(v0 * inv, v1 * inv, v2 * inv, v3 * inv);
        }
    }
}

// ---------------- cascade + projection + inverse WT (v7) ---------------------
#define C_OUT 0
#define C_ATT 17408
#define C_V0  21504
#define C_V1  23552
#define SMEM_FLOATS 25600
#define SMEM_BYTES  (SMEM_FLOATS * 4)

__global__ __launch_bounds__(512, 2)
void wwa_casc(const float* __restrict__ pbias, const float* __restrict__ iwt,
              float* __restrict__ out) {
    extern __shared__ float sm[];
    const int t = threadIdx.x;
    const int w = blockIdx.x;
    const int b = w >> 8, wy = (w >> 4) & 15, wx = w & 15;
    const float* subw0 = g_sub + (size_t)w * 16384;
    const float* subw1 = g_sub + ((size_t)BN + w) * 16384;
    const float* subw2 = g_sub + ((size_t)2 * BN + w) * 16384;
    const float* subw3 = g_sub + ((size_t)3 * BN + w) * 16384;

    // ============ phase 1: cascade AV (swizzled V, double-buffered) ============
    const int d = t & 31, n0g = t >> 5;
    const int n0 = n0g * 4;
    const int sw = d & 15;
    const int vslot = d * 64 + 4 * (n0g ^ sw);
    const float4* llp4 = (const float4*)subw0;
    const float4* atp4 = (const float4*)(g_attn + (size_t)(w << 3) * 4096);

    float4 at0 = atp4[t];
    float4 at1 = atp4[t + 512];
    float4 llnext = __ldg(&llp4[d * 16 + n0g]);

#pragma unroll 1
    for (int i = 0; i < 8; i++) {
        ((float4*)&sm[C_ATT])[t]       = at0;
        ((float4*)&sm[C_ATT])[t + 512] = at1;
        if (i == 0)
            *(float4*)&sm[C_V0 + vslot] = llnext;
        __syncthreads();
        if (i < 7) {
            at0 = atp4[(i + 1) * 1024 + t];
            at1 = atp4[(i + 1) * 1024 + t + 512];
            llnext = __ldg(&llp4[(i + 1) * 512 + d * 16 + n0g]);
        }

        const int vb_off = (i & 1) ? C_V1 : C_V0;
        u64 acc[4] = {};
#pragma unroll
        for (int g = 0; g < 8; g++) {
            longlong2 va = *(const longlong2*)&sm[vb_off + d * 64 + 4 * ((2 * g) ^ sw)];
            longlong2 vb = *(const longlong2*)&sm[vb_off + d * 64 + 4 * ((2 * g + 1) ^ sw)];
#pragma unroll
            for (int j = 0; j < 4; j++) {
                const longlong2* ar = (const longlong2*)&sm[C_ATT + (n0 + j) * 64 + 8 * g];
                longlong2 a0 = ar[0], a1 = ar[1];
                fma2(acc[j], (u64)va.x, (u64)a0.x);
                fma2(acc[j], (u64)va.y, (u64)a0.y);
                fma2(acc[j], (u64)vb.x, (u64)a1.x);
                fma2(acc[j], (u64)vb.y, (u64)a1.y);
            }
        }
        float v0l, v0h, v1l, v1h, v2l, v2h, v3l, v3h;
        unpack2(acc[0], v0l, v0h); unpack2(acc[1], v1l, v1h);
        unpack2(acc[2], v2l, v2h); unpack2(acc[3], v3l, v3h);
        float4 raw = make_float4(v0l + v0h, v1l + v1h, v2l + v2h, v3l + v3h);
        *(float4*)&sm[C_OUT + (i * 32 + d) * 68 + n0] =
            make_float4(fmaxf(raw.x, 0.f), fmaxf(raw.y, 0.f),
                        fmaxf(raw.z, 0.f), fmaxf(raw.w, 0.f));
        if (i < 7) {
            float4 vn = make_float4(raw.x + llnext.x, raw.y + llnext.y,
                                    raw.z + llnext.z, raw.w + llnext.w);
            int alt = (i & 1) ? C_V0 : C_V1;
            *(float4*)&sm[alt + vslot] = vn;
        }
        __syncthreads();
    }

    // ============ phase 2: projection, 4 o's x 8 px per thread ================
    const int oa = t & 63, q = t >> 6;
    const int nb = q * 8;
    u64 acc[4][4];
#pragma unroll
    for (int j = 0; j < 4; j++) {
        float pbv = pbias[oa + 64 * j];
        u64 pi = pack2(pbv, pbv);
#pragma unroll
        for (int u = 0; u < 4; u++) acc[j][u] = pi;
    }
    const float4* wq = ((const float4*)g_pwQ) + oa;
#pragma unroll 4
    for (int c = 0; c < 256; c++) {
        float4 w4 = __ldg(wq + c * 64);          // w[c][oa + 64j], j=0..3
        const longlong2* row = (const longlong2*)&sm[C_OUT + c * 68 + nb];
        longlong2 pr0 = row[0], pr1 = row[1];
        u64 a0 = (u64)pr0.x, a1 = (u64)pr0.y, a2 = (u64)pr1.x, a3 = (u64)pr1.y;
        u64 w2;
        w2 = pack2(w4.x, w4.x);
        fma2(acc[0][0], w2, a0); fma2(acc[0][1], w2, a1);
        fma2(acc[0][2], w2, a2); fma2(acc[0][3], w2, a3);
        w2 = pack2(w4.y, w4.y);
        fma2(acc[1][0], w2, a0); fma2(acc[1][1], w2, a1);
        fma2(acc[1][2], w2, a2); fma2(acc[1][3], w2, a3);
        w2 = pack2(w4.z, w4.z);
        fma2(acc[2][0], w2, a0); fma2(acc[2][1], w2, a1);
        fma2(acc[2][2], w2, a2); fma2(acc[2][3], w2, a3);
        w2 = pack2(w4.w, w4.w);
        fma2(acc[3][0], w2, a0); fma2(acc[3][1], w2, a1);
        fma2(acc[3][2], w2, a2); fma2(acc[3][3], w2, a3);
    }
    __syncthreads();   // all cat reads done; C_OUT becomes P
#pragma unroll
    for (int j = 0; j < 4; j++) {
        longlong2 s0, s1;
        s0.x = (long long)acc[j][0]; s0.y = (long long)acc[j][1];
        s1.x = (long long)acc[j][2]; s1.y = (long long)acc[j][3];
        *(longlong2*)&sm[C_OUT + (oa + 64 * j) * 68 + nb]     = s0;
        *(longlong2*)&sm[C_OUT + (oa + 64 * j) * 68 + nb + 4] = s1;
    }
    __syncthreads();   // P visible to all

    // ============ phase 3: inverse WT epilogue (barrier-free, direct LDG) ======
    const int oo = t >> 4, m = t & 15;
    const int py = m >> 1, ry = m & 1;
    float* obase = out + (size_t)(b * DIM) * RES * RES
                 + (size_t)(wy * 16 + m) * RES + wx * 16;

#pragma unroll 1
    for (int obk = 0; obk < 8; obk++) {
        const int og = obk * 32 + oo;
        const float* iwp = iwt + og * 16 + 2 * ry;
        float c00 = __ldg(iwp + 0),  c01 = __ldg(iwp + 1);
        float c10 = __ldg(iwp + 4),  c11 = __ldg(iwp + 5);
        float c20 = __ldg(iwp + 8),  c21 = __ldg(iwp + 9);
        float c30 = __ldg(iwp + 12), c31 = __ldg(iwp + 13);
        const int nb2 = og * 64 + 8 * py;
        float4 lhA = __ldg((const float4*)(subw1 + nb2));
        float4 lhB = __ldg((const float4*)(subw1 + nb2 + 4));
        float4 hlA = __ldg((const float4*)(subw2 + nb2));
        float4 hlB = __ldg((const float4*)(subw2 + nb2 + 4));
        float4 hhA = __ldg((const float4*)(subw3 + nb2));
        float4 hhB = __ldg((const float4*)(subw3 + nb2 + 4));
        float4 pA = *(const float4*)&sm[C_OUT + og * 68 + 8 * py];
        float4 pB = *(const float4*)&sm[C_OUT + og * 68 + 8 * py + 4];
        float* orow = obase + (size_t)og * (RES * RES);

        float4 r0, r1, r2, r3;
        r0.x = pA.x * c00 + lhA.x * c10 + hlA.x * c20 + hhA.x * c30;
        r0.y = pA.x * c01 + lhA.x * c11 + hlA.x * c21 + hhA.x * c31;
        r0.z = pA.y * c00 + lhA.y * c10 + hlA.y * c20 + hhA.y * c30;
        r0.w = pA.y * c01 + lhA.y * c11 + hlA.y * c21 + hhA.y * c31;
        r1.x = pA.z * c00 + lhA.z * c10 + hlA.z * c20 + hhA.z * c30;
        r1.y = pA.z * c01 + lhA.z * c11 + hlA.z * c21 + hhA.z * c31;
        r1.z = pA.w * c00 + lhA.w * c10 + hlA.w * c20 + hhA.w * c30;
        r1.w = pA.w * c01 + lhA.w * c11 + hlA.w * c21 + hhA.w * c31;
        r2.x = pB.x * c00 + lhB.x * c10 + hlB.x * c20 + hhB.x * c30;
        r2.y = pB.x * c01 + lhB.x * c11 + hlB.x * c21 + hhB.x * c31;
        r2.z = pB.y * c00 + lhB.y * c10 + hlB.y * c20 + hhB.y * c30;
        r2.w = pB.y * c01 + lhB.y * c11 + hlB.y * c21 + hhB.y * c31;
        r3.x = pB.z * c00 + lhB.z * c10 + hlB.z * c20 + hhB.z * c30;
        r3.y = pB.z * c01 + lhB.z * c11 + hlB.z * c21 + hhB.z * c31;
        r3.z = pB.w * c00 + lhB.w * c10 + hlB.w * c20 + hhB.w * c30;
        r3.w = pB.w * c01 + lhB.w * c11 + hlB.w * c21 + hhB.w * c31;
        *(float4*)&orow[0]  = r0;
        *(float4*)&orow[4]  = r1;
        *(float4*)&orow[8]  = r2;
        *(float4*)&orow[12] = r3;
    }
}

extern "C" void kernel_launch(void* const* d_in, const int* in_sizes, int n_in,
                              void* d_out, int out_size) {
    const float* x    = (const float*)d_in[0];
    const float* wtf  = (const float*)d_in[1];
    const float* iwtf = (const float*)d_in[2];
    const float* dww  = (const float*)d_in[3];
    const float* dwb  = (const float*)d_in[4];
    const float* pw   = (const float*)d_in[5];
    const float* pb   = (const float*)d_in[6];
    const float* ab   = (const float*)d_in[7];
    const int*   idxs = (const int*)d_in[8];
    int n_off = in_sizes[7] / HEADS;
    float* out = (float*)d_out;

    cudaFuncSetAttribute(wwa_attn, cudaFuncAttributeMaxDynamicSharedMemorySize, ATTN_SMEM_BYTES);
    cudaFuncSetAttribute(wwa_casc, cudaFuncAttributeMaxDynamicSharedMemorySize, SMEM_BYTES);

    wwa_prep<<<256, 256>>>(ab, idxs, n_off, pw);
    wwa_wt<<<16384, 256>>>(x, wtf);
    wwa_attn<<<BN * HEADS, 256, ATTN_SMEM_BYTES>>>(dww, dwb);
    wwa_casc<<<BN, 512, SMEM_BYTES>>>(pb, iwtf, out);
}

// round 14
// speedup vs baseline: 1.7782x; 1.0528x over previous
#include <cuda_runtime.h>

#define BATCH 2
#define DIM   256
#define HEADS 8
#define HD    32
#define RES   256
#define FWS   8
#define BN    512            // BATCH * 16 * 16 windows
#define NPIX  64
#define ATTN_SCALE 0.17677669529663689f

// ---------------- device scratch ----------------
__device__ float g_sub[(size_t)4 * BN * DIM * NPIX];          // [s][w][c][n]  134.2 MB
__device__ float g_bias[HEADS * NPIX * NPIX];                 // 128 KB
__device__ float g_attn[(size_t)BN * HEADS * NPIX * NPIX];    // softmaxed attn, 67 MB
__device__ float g_pwQ[DIM * DIM];                            // quad-interleaved proj weight
                                                              // g_pwQ[(c*64 + (o&63))*4 + (o>>6)] = pw[o][c]

typedef unsigned long long u64;

__device__ __forceinline__ u64 pack2(float lo, float hi) {
    u64 r; asm("mov.b64 %0,{%1,%2};" : "=l"(r) : "f"(lo), "f"(hi)); return r;
}
__device__ __forceinline__ void unpack2(u64 v, float& a, float& b) {
    asm("mov.b64 {%0,%1},%2;" : "=f"(a), "=f"(b) : "l"(v));
}
__device__ __forceinline__ void fma2(u64& d, u64 a, u64 b) {
    asm("fma.rn.f32x2 %0,%1,%2,%0;" : "+l"(d) : "l"(a), "l"(b));
}

// ---------------- prep: bias gather + proj weight quad-interleave ------------
__global__ void wwa_prep(const float* __restrict__ ab, const int* __restrict__ idxs,
                         int n_off, const float* __restrict__ pw) {
    int blk = blockIdx.x, t = threadIdx.x;
    if (blk < 128) {
        int idx = blk * 256 + t;                 // 0..32767
        int i = idx >> 12, r = idx & 4095;
        g_bias[idx] = ab[i * n_off + idxs[r]];
    } else {
        int base = (blk - 128) * 512;
#pragma unroll
        for (int rep = 0; rep < 2; rep++) {
            int u = base + t + rep * 256;        // 0..65535, coalesced read
            int o = u >> 8, c = u & 255;
            g_pwQ[(c * 64 + (o & 63)) * 4 + (o >> 6)] = pw[u];
        }
    }
}

// ---------------- wavelet transform ----------------
__global__ void wwa_wt(const float* __restrict__ x, const float* __restrict__ wf) {
    int g = blockIdx.x * 256 + threadIdx.x;
    int pair = g & 31;
    int c = (g >> 5) & 255;
    int w = g >> 13;
    int b = w >> 8, wy = (w >> 4) & 15, wx = w & 15;
    int n0 = pair * 2;
    int p = wy * 8 + (n0 >> 3);
    int q0 = wx * 8 + (n0 & 7);
    const float* xp = x + ((size_t)(b * DIM + c) * RES + 2 * p) * RES + 2 * q0;
    float4 r0 = *(const float4*)xp;
    float4 r1 = *(const float4*)(xp + RES);
    const float4* wf4 = (const float4*)wf;
    float* dst = g_sub + ((size_t)w * DIM + c) * NPIX + n0;
#pragma unroll
    for (int s = 0; s < 4; s++) {
        float4 f = wf4[4 * c + s];
        float o0 = r0.x * f.x + r0.y * f.y + r1.x * f.z + r1.y * f.w;
        float o1 = r0.z * f.x + r0.w * f.y + r1.z * f.z + r1.w * f.w;
        *(float2*)(dst + (size_t)s * BN * DIM * NPIX) = make_float2(o0, o1);
    }
}

// ---------------- attention precompute (unchanged, R9-proven) ----------------
#define A_T   0
#define A_DWW 6272
#define A_DWB 7072
#define A_Q   7104
#define A_K   11456
#define A_TOT 13632
#define ATTN_SMEM_BYTES (A_TOT * 4)

__global__ __launch_bounds__(256)
void wwa_attn(const float* __restrict__ dww, const float* __restrict__ dwb) {
    extern __shared__ float sm[];
    const int t = threadIdx.x;
    const int wh = blockIdx.x;
    const int w = wh >> 3, i = wh & 7;
    const float4* lhp4 = (const float4*)(g_sub + ((size_t)BN + w) * 16384 + i * 2048);
    const float4* hlp4 = (const float4*)(g_sub + ((size_t)2 * BN + w) * 16384 + i * 2048);

    for (int k = t; k < 1568; k += 256)
        ((float4*)sm)[k] = make_float4(0.f, 0.f, 0.f, 0.f);
    __syncthreads();
    for (int k = t; k < 512; k += 256) {
        float4 v = lhp4[k];
        int c = k >> 4, n0 = (k & 15) * 4;
        int off = A_T + c * 196 + ((n0 >> 3) + 2) * 16 + (n0 & 7) + 2;
        *(float2*)&sm[off]     = make_float2(v.x, v.y);
        *(float2*)&sm[off + 2] = make_float2(v.z, v.w);
        float4 u = hlp4[k];
        *(float4*)&sm[A_K + c * 68 + n0] = u;
    }
    for (int k = t; k < 800; k += 256) sm[A_DWW + k] = dww[i * 800 + k];
    if (t < 32) sm[A_DWB + t] = dwb[i * 32 + t];
    __syncthreads();

    {
        const int d = t & 31, py = t >> 5;
        float acc[8];
        float bb = sm[A_DWB + d];
#pragma unroll
        for (int qx = 0; qx < 8; qx++) acc[qx] = bb;
        const float* wp = &sm[A_DWW + d * 25];
        const float* tp = &sm[A_T + d * 196 + py * 16];
#pragma unroll
        for (int ii = 0; ii < 5; ii++) {
            float4 ra = *(const float4*)&tp[ii * 16];
            float4 rb = *(const float4*)&tp[ii * 16 + 4];
            float4 rc = *(const float4*)&tp[ii * 16 + 8];
            float row[12] = {ra.x, ra.y, ra.z, ra.w,
                             rb.x, rb.y, rb.z, rb.w,
                             rc.x, rc.y, rc.z, rc.w};
#pragma unroll
            for (int jj = 0; jj < 5; jj++) {
                float wv = wp[ii * 5 + jj];
#pragma unroll
                for (int qx = 0; qx < 8; qx++)
                    acc[qx] += row[qx + jj] * wv;
            }
        }
#pragma unroll
        for (int qx = 0; qx < 8; qx++) {
            int n = py * 8 + qx;
            *(u64*)&sm[A_Q + n * 68 + 2 * d] = pack2(acc[qx], acc[qx]);
        }
    }
    __syncthreads();

    {
        const int rg = t >> 4, cg = t & 15, m0 = cg * 4;
        u64 acc[4][2] = {};
#pragma unroll 4
        for (int d = 0; d < 32; d += 2) {
            longlong2 ka = *(const longlong2*)&sm[A_K + d * 68 + m0];
            longlong2 kb = *(const longlong2*)&sm[A_K + (d + 1) * 68 + m0];
#pragma unroll
            for (int r = 0; r < 4; r++) {
                longlong2 q2 = *(const longlong2*)&sm[A_Q + (rg * 4 + r) * 68 + 2 * d];
                fma2(acc[r][0], (u64)q2.x, (u64)ka.x);
                fma2(acc[r][1], (u64)q2.x, (u64)ka.y);
                fma2(acc[r][0], (u64)q2.y, (u64)kb.x);
                fma2(acc[r][1], (u64)q2.y, (u64)kb.y);
            }
        }
        float* ap = g_attn + (size_t)wh * 4096;
#pragma unroll
        for (int r = 0; r < 4; r++) {
            int n = rg * 4 + r;
            float v0, v1, v2, v3;
            unpack2(acc[r][0], v0, v1);
            unpack2(acc[r][1], v2, v3);
            const float4 bv = *(const float4*)&g_bias[i * 4096 + n * 64 + m0];
            v0 = v0 * ATTN_SCALE + bv.x; v1 = v1 * ATTN_SCALE + bv.y;
            v2 = v2 * ATTN_SCALE + bv.z; v3 = v3 * ATTN_SCALE + bv.w;
            float mx = fmaxf(fmaxf(v0, v1), fmaxf(v2, v3));
#pragma unroll
            for (int off = 8; off >= 1; off >>= 1)
                mx = fmaxf(mx, __shfl_xor_sync(0xffffffffu, mx, off));
            v0 = __expf(v0 - mx); v1 = __expf(v1 - mx);
            v2 = __expf(v2 - mx); v3 = __expf(v3 - mx);
            float s = v0 + v1 + v2 + v3;
#pragma unroll
            for (int off = 8; off >= 1; off >>= 1)
                s += __shfl_xor_sync(0xffffffffu, s, off);
            float inv = __fdividef(1.f, s);
            *(float4*)&ap[n * 64 + m0] = make_float4(v0 * inv, v1 * inv, v2 * inv, v3 * inv);
        }
    }
}

// ---------------- cascade + projection + inverse WT (v8) ---------------------
#define C_OUT 0
#define C_ATT 17408
#define C_V0  21504
#define C_V1  23552
#define SMEM_FLOATS 25600
#define SMEM_BYTES  (SMEM_FLOATS * 4)

__global__ __launch_bounds__(512, 2)
void wwa_casc(const float* __restrict__ pbias, const float* __restrict__ iwt,
              float* __restrict__ out) {
    extern __shared__ float sm[];
    const int t = threadIdx.x;
    const int w = blockIdx.x;
    const int b = w >> 8, wy = (w >> 4) & 15, wx = w & 15;
    const float* subw0 = g_sub + (size_t)w * 16384;
    const float* subw1 = g_sub + ((size_t)BN + w) * 16384;
    const float* subw2 = g_sub + ((size_t)2 * BN + w) * 16384;
    const float* subw3 = g_sub + ((size_t)3 * BN + w) * 16384;

    // ============ phase 1: cascade AV (swizzled V, double-buffered) ============
    const int d = t & 31, n0g = t >> 5;
    const int n0 = n0g * 4;
    const int sw = d & 15;
    const int vslot = d * 64 + 4 * (n0g ^ sw);
    const float4* llp4 = (const float4*)subw0;
    const float4* atp4 = (const float4*)(g_attn + (size_t)(w << 3) * 4096);

    float4 at0 = atp4[t];
    float4 at1 = atp4[t + 512];
    float4 llnext = __ldg(&llp4[d * 16 + n0g]);

#pragma unroll 1
    for (int i = 0; i < 8; i++) {
        ((float4*)&sm[C_ATT])[t]       = at0;
        ((float4*)&sm[C_ATT])[t + 512] = at1;
        if (i == 0)
            *(float4*)&sm[C_V0 + vslot] = llnext;
        __syncthreads();
        if (i < 7) {
            at0 = atp4[(i + 1) * 1024 + t];
            at1 = atp4[(i + 1) * 1024 + t + 512];
            llnext = __ldg(&llp4[(i + 1) * 512 + d * 16 + n0g]);
        }

        const int vb_off = (i & 1) ? C_V1 : C_V0;
        u64 acc[4] = {};
#pragma unroll
        for (int g = 0; g < 8; g++) {
            longlong2 va = *(const longlong2*)&sm[vb_off + d * 64 + 4 * ((2 * g) ^ sw)];
            longlong2 vb = *(const longlong2*)&sm[vb_off + d * 64 + 4 * ((2 * g + 1) ^ sw)];
#pragma unroll
            for (int j = 0; j < 4; j++) {
                const longlong2* ar = (const longlong2*)&sm[C_ATT + (n0 + j) * 64 + 8 * g];
                longlong2 a0 = ar[0], a1 = ar[1];
                fma2(acc[j], (u64)va.x, (u64)a0.x);
                fma2(acc[j], (u64)va.y, (u64)a0.y);
                fma2(acc[j], (u64)vb.x, (u64)a1.x);
                fma2(acc[j], (u64)vb.y, (u64)a1.y);
            }
        }
        float v0l, v0h, v1l, v1h, v2l, v2h, v3l, v3h;
        unpack2(acc[0], v0l, v0h); unpack2(acc[1], v1l, v1h);
        unpack2(acc[2], v2l, v2h); unpack2(acc[3], v3l, v3h);
        float4 raw = make_float4(v0l + v0h, v1l + v1h, v2l + v2h, v3l + v3h);
        *(float4*)&sm[C_OUT + (i * 32 + d) * 68 + n0] =
            make_float4(fmaxf(raw.x, 0.f), fmaxf(raw.y, 0.f),
                        fmaxf(raw.z, 0.f), fmaxf(raw.w, 0.f));
        if (i < 7) {
            float4 vn = make_float4(raw.x + llnext.x, raw.y + llnext.y,
                                    raw.z + llnext.z, raw.w + llnext.w);
            int alt = (i & 1) ? C_V0 : C_V1;
            *(float4*)&sm[alt + vslot] = vn;
        }
        __syncthreads();
    }

    // ============ phase 2: projection, 4 o's x 8 px per thread ================
    const int oa = t & 63, q = t >> 6;
    const int nb = q * 8;
    u64 acc[4][4];
#pragma unroll
    for (int j = 0; j < 4; j++) {
        float pbv = pbias[oa + 64 * j];
        u64 pi = pack2(pbv, pbv);
#pragma unroll
        for (int u = 0; u < 4; u++) acc[j][u] = pi;
    }
    const float4* wq = ((const float4*)g_pwQ) + oa;
#pragma unroll 4
    for (int c = 0; c < 256; c++) {
        float4 w4 = __ldg(wq + c * 64);          // w[c][oa + 64j], j=0..3
        const longlong2* row = (const longlong2*)&sm[C_OUT + c * 68 + nb];
        longlong2 pr0 = row[0], pr1 = row[1];
        u64 a0 = (u64)pr0.x, a1 = (u64)pr0.y, a2 = (u64)pr1.x, a3 = (u64)pr1.y;
        u64 w2;
        w2 = pack2(w4.x, w4.x);
        fma2(acc[0][0], w2, a0); fma2(acc[0][1], w2, a1);
        fma2(acc[0][2], w2, a2); fma2(acc[0][3], w2, a3);
        w2 = pack2(w4.y, w4.y);
        fma2(acc[1][0], w2, a0); fma2(acc[1][1], w2, a1);
        fma2(acc[1][2], w2, a2); fma2(acc[1][3], w2, a3);
        w2 = pack2(w4.z, w4.z);
        fma2(acc[2][0], w2, a0); fma2(acc[2][1], w2, a1);
        fma2(acc[2][2], w2, a2); fma2(acc[2][3], w2, a3);
        w2 = pack2(w4.w, w4.w);
        fma2(acc[3][0], w2, a0); fma2(acc[3][1], w2, a1);
        fma2(acc[3][2], w2, a2); fma2(acc[3][3], w2, a3);
    }
    __syncthreads();   // all cat reads done; C_OUT becomes P
#pragma unroll
    for (int j = 0; j < 4; j++) {
        longlong2 s0, s1;
        s0.x = (long long)acc[j][0]; s0.y = (long long)acc[j][1];
        s1.x = (long long)acc[j][2]; s1.y = (long long)acc[j][3];
        *(longlong2*)&sm[C_OUT + (oa + 64 * j) * 68 + nb]     = s0;
        *(longlong2*)&sm[C_OUT + (oa + 64 * j) * 68 + nb + 4] = s1;
    }
    __syncthreads();   // P visible to all

    // ============ phase 3: inverse WT epilogue (warp = one og per store) =======
    const int xq = t & 3;              // x chunk: out x = 4*xq .. 4*xq+3
    const int row8 = (t >> 2) & 7;     // row subgroup
    const int wid = t >> 5;            // warp id 0..15
    const int ry = row8 & 1;           // sub-row parity (r-independent)
    float* ob = out + (size_t)(b * DIM) * RES * RES
              + (size_t)(wy * 16) * RES + wx * 16 + 4 * xq;

#pragma unroll 1
    for (int obk = 0; obk < 8; obk++) {
#pragma unroll
        for (int s = 0; s < 2; s++) {
            const int og = obk * 32 + wid * 2 + s;
            const float* iwp = iwt + og * 16 + 2 * ry;
            float c00 = __ldg(iwp + 0),  c01 = __ldg(iwp + 1);
            float c10 = __ldg(iwp + 4),  c11 = __ldg(iwp + 5);
            float c20 = __ldg(iwp + 8),  c21 = __ldg(iwp + 9);
            float c30 = __ldg(iwp + 12), c31 = __ldg(iwp + 13);
            float* oc = ob + (size_t)og * (RES * RES);
#pragma unroll
            for (int r = 0; r < 2; r++) {
                const int row = row8 + 8 * r;            // 0..15
                const int py = row >> 1;
                const int n = 8 * py + 2 * xq;           // source pixel pair
                float2 a  = *(const float2*)&sm[C_OUT + og * 68 + n];
                float2 lh = __ldg((const float2*)(subw1 + og * 64 + n));
                float2 hl = __ldg((const float2*)(subw2 + og * 64 + n));
                float2 hh = __ldg((const float2*)(subw3 + og * 64 + n));
                float4 rr;
                rr.x = a.x * c00 + lh.x * c10 + hl.x * c20 + hh.x * c30;
                rr.y = a.x * c01 + lh.x * c11 + hl.x * c21 + hh.x * c31;
                rr.z = a.y * c00 + lh.y * c10 + hl.y * c20 + hh.y * c30;
                rr.w = a.y * c01 + lh.y * c11 + hl.y * c21 + hh.y * c31;
                *(float4*)(oc + (size_t)row * RES) = rr;
            }
        }
    }
}

extern "C" void kernel_launch(void* const* d_in, const int* in_sizes, int n_in,
                              void* d_out, int out_size) {
    const float* x    = (const float*)d_in[0];
    const float* wtf  = (const float*)d_in[1];
    const float* iwtf = (const float*)d_in[2];
    const float* dww  = (const float*)d_in[3];
    const float* dwb  = (const float*)d_in[4];
    const float* pw   = (const float*)d_in[5];
    const float* pb   = (const float*)d_in[6];
    const float* ab   = (const float*)d_in[7];
    const int*   idxs = (const int*)d_in[8];
    int n_off = in_sizes[7] / HEADS;
    float* out = (float*)d_out;

    cudaFuncSetAttribute(wwa_attn, cudaFuncAttributeMaxDynamicSharedMemorySize, ATTN_SMEM_BYTES);
    cudaFuncSetAttribute(wwa_casc, cudaFuncAttributeMaxDynamicSharedMemorySize, SMEM_BYTES);

    wwa_prep<<<256, 256>>>(ab, idxs, n_off, pw);
    wwa_wt<<<16384, 256>>>(x, wtf);
    wwa_attn<<<BN * HEADS, 256, ATTN_SMEM_BYTES>>>(dww, dwb);
    wwa_casc<<<BN, 512, SMEM_BYTES>>>(pb, iwtf, out);
}